// round 8
// baseline (speedup 1.0000x reference)
#include <cuda_runtime.h>
#include <math.h>

// B=2, S=2048, D=1024, H=16, HD=64. Scratch: row-major [b*S+s][h*64+e].
__device__ float n_q[4096*1024];
__device__ float n_k[4096*1024];
__device__ float n_v[4096*1024];
__device__ float n_ctx[4096*1024];

// ---------------------------------------------------------------------------
// Naive GEMM: C[4096,1024] = A @ W^T (row-major). One output per thread,
// float4 k-loop. block (16,16): A-row broadcast over tx, W-row over ty (L1).
// ---------------------------------------------------------------------------
__global__ void ngemm(const float* __restrict__ A, const float* __restrict__ W,
                      float* __restrict__ C)
{
    const int n = blockIdx.x * 16 + threadIdx.x;
    const int m = blockIdx.y * 16 + threadIdx.y;
    const float4* a4 = (const float4*)(A + m * 1024);
    const float4* w4 = (const float4*)(W + n * 1024);
    float acc = 0.0f;
    for (int k = 0; k < 256; k++) {
        float4 a = a4[k];
        float4 w = w4[k];
        acc += a.x * w.x + a.y * w.y + a.z * w.z + a.w * w.w;
    }
    C[m * 1024 + n] = acc;
}

// ---------------------------------------------------------------------------
// Naive RoPE, in place. Thread per (m, h, i), i = 0..31.
//   angle = s * 10000^(-i/32);  pair (h*64+i, h*64+i+32):
//   new1 = x1*cos - x2*sin ; new2 = x2*cos + x1*sin
// ---------------------------------------------------------------------------
__global__ void nrope(float* q, float* k)
{
    const int g = blockIdx.x * 256 + threadIdx.x;  // < 4096*16*32
    const int i = g & 31;
    const int h = (g >> 5) & 15;
    const int m = g >> 9;          // 0..4095
    const int s = m & 2047;
    const float freq = powf(10000.0f, -(float)i / 32.0f);
    const float ang  = (float)s * freq;
    const float c = cosf(ang), sn = sinf(ang);
    const int o = m * 1024 + h * 64 + i;
    float x1 = q[o], x2 = q[o + 32];
    q[o]      = x1 * c - x2 * sn;
    q[o + 32] = x2 * c + x1 * sn;
    x1 = k[o]; x2 = k[o + 32];
    k[o]      = x1 * c - x2 * sn;
    k[o + 32] = x2 * c + x1 * sn;
}

// ---------------------------------------------------------------------------
// Naive attention. Block per (query row m, head h); 256 threads.
// Full 2048-score row in smem; two-pass softmax via block reductions; PV with
// 4-way key split. No shuffles, no online softmax.
// ---------------------------------------------------------------------------
__global__ void __launch_bounds__(256) nattn(const float* __restrict__ q,
                                             const float* __restrict__ k,
                                             const float* __restrict__ v,
                                             float* __restrict__ ctx)
{
    __shared__ float sc[2048];
    __shared__ float qs[64];
    __shared__ float red[256];

    const int m = blockIdx.x;      // b*2048 + s
    const int h = blockIdx.y;
    const int b = m >> 11;
    const int t = threadIdx.x;

    const float* kbase = k + (b * 2048) * 1024 + h * 64;
    const float* vbase = v + (b * 2048) * 1024 + h * 64;

    if (t < 64) qs[t] = q[m * 1024 + h * 64 + t] * 0.125f;  // 1/sqrt(64)
    __syncthreads();

    // Scores: 8 keys per thread
    for (int kk = 0; kk < 8; kk++) {
        const int tkey = t * 8 + kk;
        const float* kr = kbase + tkey * 1024;
        float acc = 0.0f;
        for (int d = 0; d < 64; d++) acc += qs[d] * kr[d];
        sc[tkey] = acc;
    }
    __syncthreads();

    // Block max
    float lm = -1e30f;
    for (int kk = 0; kk < 8; kk++) lm = fmaxf(lm, sc[t * 8 + kk]);
    red[t] = lm;
    __syncthreads();
    for (int o = 128; o > 0; o >>= 1) {
        if (t < o) red[t] = fmaxf(red[t], red[t + o]);
        __syncthreads();
    }
    const float mx = red[0];
    __syncthreads();

    // exp + block sum
    float ls = 0.0f;
    for (int kk = 0; kk < 8; kk++) {
        const float p = expf(sc[t * 8 + kk] - mx);
        sc[t * 8 + kk] = p;
        ls += p;
    }
    red[t] = ls;
    __syncthreads();
    for (int o = 128; o > 0; o >>= 1) {
        if (t < o) red[t] += red[t + o];
        __syncthreads();
    }
    const float inv = 1.0f / red[0];
    __syncthreads();   // everyone has read red[0] before red is reused

    // PV: thread = (e = t&63, quarter = t>>6); each sums 512 keys
    const int e = t & 63, qq = t >> 6;
    float acc = 0.0f;
    const int k0 = qq * 512;
    for (int tkey = k0; tkey < k0 + 512; tkey++)
        acc += sc[tkey] * vbase[tkey * 1024 + e];
    red[qq * 64 + e] = acc;
    __syncthreads();

    if (t < 64) {
        const float r = (red[t] + red[64 + t] + red[128 + t] + red[192 + t]) * inv;
        ctx[m * 1024 + h * 64 + t] = r;
    }
}

// ---------------------------------------------------------------------------
extern "C" void kernel_launch(void* const* d_in, const int* in_sizes, int n_in,
                              void* d_out, int out_size)
{
    const float* x  = (const float*)d_in[0];
    const float* Wq = (const float*)d_in[1];
    const float* Wk = (const float*)d_in[2];
    const float* Wv = (const float*)d_in[3];
    const float* Wo = (const float*)d_in[4];
    float* out = (float*)d_out;

    float* gq;  cudaGetSymbolAddress((void**)&gq, n_q);
    float* gk;  cudaGetSymbolAddress((void**)&gk, n_k);
    float* gv;  cudaGetSymbolAddress((void**)&gv, n_v);
    float* gc;  cudaGetSymbolAddress((void**)&gc, n_ctx);

    dim3 gb(16, 16);
    dim3 gg(64, 256);                 // (N/16, M/16)
    ngemm<<<gg, gb>>>(x, Wq, gq);
    ngemm<<<gg, gb>>>(x, Wk, gk);
    ngemm<<<gg, gb>>>(x, Wv, gv);
    nrope<<<4096 * 16 * 32 / 256, 256>>>(gq, gk);
    nattn<<<dim3(4096, 16), 256>>>(gq, gk, gv, gc);
    ngemm<<<gg, gb>>>(gc, Wo, out);
}

// round 9
// speedup vs baseline: 20.1580x; 20.1580x over previous
#include <cuda_runtime.h>
#include <math.h>

// B=2, S=2048, D=1024, H=16, HD=64. Scratch: row-major [b*S+s][h*64+e].
__device__ float n_q[4096*1024];
__device__ float n_k[4096*1024];
__device__ float n_v[4096*1024];
__device__ float n_ctx[4096*1024];

// ---------------------------------------------------------------------------
// Tiled GEMM: C[4096,1024] = A @ W^T (row-major). 128x128 tile, BK=16,
// 256 threads, 8x8 microtile, padded k-major smem (LDP=132).
// Audited: semantically identical to the naive ngemm that passed in R8.
// ---------------------------------------------------------------------------
#define LDP 132

__global__ void __launch_bounds__(256) gemm_k(const float* __restrict__ A,
                                              const float* __restrict__ W,
                                              float* __restrict__ C)
{
    __shared__ float As[16 * LDP];
    __shared__ float Bs[16 * LDP];

    const int t  = threadIdx.x;
    const int tx = t & 15, ty = t >> 4;
    const int m0 = blockIdx.y << 7;
    const int n0 = blockIdx.x << 7;

    const int row0 = t >> 2;          // 0..63
    const int kg   = (t & 3) << 2;    // 0,4,8,12

    float acc[8][8];
#pragma unroll
    for (int i = 0; i < 8; i++)
#pragma unroll
        for (int j = 0; j < 8; j++) acc[i][j] = 0.f;

    for (int k0 = 0; k0 < 1024; k0 += 16) {
        float4 a0v = *(const float4*)(A + (m0 + row0)      * 1024 + k0 + kg);
        float4 a1v = *(const float4*)(A + (m0 + row0 + 64) * 1024 + k0 + kg);
        float4 b0v = *(const float4*)(W + (n0 + row0)      * 1024 + k0 + kg);
        float4 b1v = *(const float4*)(W + (n0 + row0 + 64) * 1024 + k0 + kg);

        __syncthreads();   // previous iteration's smem reads complete

        As[(kg+0)*LDP + row0] = a0v.x;
        As[(kg+1)*LDP + row0] = a0v.y;
        As[(kg+2)*LDP + row0] = a0v.z;
        As[(kg+3)*LDP + row0] = a0v.w;
        As[(kg+0)*LDP + row0 + 64] = a1v.x;
        As[(kg+1)*LDP + row0 + 64] = a1v.y;
        As[(kg+2)*LDP + row0 + 64] = a1v.z;
        As[(kg+3)*LDP + row0 + 64] = a1v.w;
        Bs[(kg+0)*LDP + row0] = b0v.x;
        Bs[(kg+1)*LDP + row0] = b0v.y;
        Bs[(kg+2)*LDP + row0] = b0v.z;
        Bs[(kg+3)*LDP + row0] = b0v.w;
        Bs[(kg+0)*LDP + row0 + 64] = b1v.x;
        Bs[(kg+1)*LDP + row0 + 64] = b1v.y;
        Bs[(kg+2)*LDP + row0 + 64] = b1v.z;
        Bs[(kg+3)*LDP + row0 + 64] = b1v.w;

        __syncthreads();   // tile ready

#pragma unroll
        for (int kk = 0; kk < 16; kk++) {
            float4 a0 = *(const float4*)&As[kk*LDP + (ty << 2)];
            float4 a1 = *(const float4*)&As[kk*LDP + 64 + (ty << 2)];
            float4 b0 = *(const float4*)&Bs[kk*LDP + (tx << 2)];
            float4 b1 = *(const float4*)&Bs[kk*LDP + 64 + (tx << 2)];
            float a[8] = {a0.x,a0.y,a0.z,a0.w, a1.x,a1.y,a1.z,a1.w};
            float b[8] = {b0.x,b0.y,b0.z,b0.w, b1.x,b1.y,b1.z,b1.w};
#pragma unroll
            for (int i = 0; i < 8; i++)
#pragma unroll
                for (int j = 0; j < 8; j++)
                    acc[i][j] = fmaf(a[i], b[j], acc[i][j]);
        }
    }

#pragma unroll
    for (int ih = 0; ih < 2; ih++)
#pragma unroll
        for (int ii = 0; ii < 4; ii++) {
            const int i = ih * 4 + ii;
            const int m = m0 + ih * 64 + (ty << 2) + ii;
#pragma unroll
            for (int jh = 0; jh < 2; jh++) {
                const int n = n0 + jh * 64 + (tx << 2);
                *(float4*)&C[m * 1024 + n] =
                    make_float4(acc[i][jh*4+0], acc[i][jh*4+1],
                                acc[i][jh*4+2], acc[i][jh*4+3]);
            }
        }
}

// ---------------------------------------------------------------------------
// RoPE — VERBATIM from the passing R8 kernel. Do not touch.
// ---------------------------------------------------------------------------
__global__ void nrope(float* q, float* k)
{
    const int g = blockIdx.x * 256 + threadIdx.x;  // < 4096*16*32
    const int i = g & 31;
    const int h = (g >> 5) & 15;
    const int m = g >> 9;          // 0..4095
    const int s = m & 2047;
    const float freq = powf(10000.0f, -(float)i / 32.0f);
    const float ang  = (float)s * freq;
    const float c = cosf(ang), sn = sinf(ang);
    const int o = m * 1024 + h * 64 + i;
    float x1 = q[o], x2 = q[o + 32];
    q[o]      = x1 * c - x2 * sn;
    q[o + 32] = x2 * c + x1 * sn;
    x1 = k[o]; x2 = k[o + 32];
    k[o]      = x1 * c - x2 * sn;
    k[o + 32] = x2 * c + x1 * sn;
}

// ---------------------------------------------------------------------------
// Flash attention, thread-private rows: block = (128 q-rows, head), 128 thr.
// Each thread owns ONE q-row: private online softmax (m, l) and o[64] in
// registers -> zero cross-thread reductions. K/V staged in smem in 16-key
// tiles (coalesced float4 loads; broadcast LDS reads in compute).
// Qs stride 68 floats: 16B-aligned; per-lane distinct rows hit the LDS.128
// 4-wavefront floor with conflict-free 8-lane phases.
// ---------------------------------------------------------------------------
#define LQ2 68

__global__ void __launch_bounds__(128) fattn(const float* __restrict__ q,
                                             const float* __restrict__ k,
                                             const float* __restrict__ v,
                                             float* __restrict__ ctx)
{
    __shared__ float Qs[128 * LQ2];
    __shared__ float Ks[16 * LQ2];
    __shared__ float Vs[16 * LQ2];

    const int t  = threadIdx.x;          // 0..127 = this thread's q-row in tile
    const int qt = blockIdx.x;           // 0..15
    const int bh = blockIdx.y;           // 0..31
    const int b  = bh >> 4, h = bh & 15;

    const float* qg = q + (b * 2048 + (qt << 7)) * 1024 + (h << 6);
    const float* kg = k + (b * 2048) * 1024 + (h << 6);
    const float* vg = v + (b * 2048) * 1024 + (h << 6);

    // Load Q tile (coalesced), fold in 1/sqrt(64) = 0.125
#pragma unroll
    for (int p = 0; p < 16; p++) {
        const int idx = (p << 7) + t;
        const int r = idx >> 4, g4 = (idx & 15) << 2;
        float4 q4 = *(const float4*)(qg + r * 1024 + g4);
        q4.x *= 0.125f; q4.y *= 0.125f; q4.z *= 0.125f; q4.w *= 0.125f;
        *(float4*)&Qs[r * LQ2 + g4] = q4;
    }

    float o[64];
#pragma unroll
    for (int e = 0; e < 64; e++) o[e] = 0.f;
    float mval = -1e30f, lval = 0.f;

    for (int kt = 0; kt < 128; kt++) {
        __syncthreads();   // prev tile's Ks/Vs reads done; covers Qs on iter 0
#pragma unroll
        for (int p = 0; p < 2; p++) {
            const int idx = (p << 7) + t;
            const int r = idx >> 4, g4 = (idx & 15) << 2;
            *(float4*)&Ks[r * LQ2 + g4] = *(const float4*)(kg + ((kt << 4) + r) * 1024 + g4);
            *(float4*)&Vs[r * LQ2 + g4] = *(const float4*)(vg + ((kt << 4) + r) * 1024 + g4);
        }
        __syncthreads();

        // Scores for 16 keys (private to this thread's row)
        float s[16];
#pragma unroll
        for (int j = 0; j < 16; j++) s[j] = 0.f;
#pragma unroll
        for (int c = 0; c < 4; c++) {        // d-chunks of 16
            float qc[16];
#pragma unroll
            for (int u = 0; u < 4; u++)
                *(float4*)&qc[u << 2] = *(const float4*)&Qs[t * LQ2 + (c << 4) + (u << 2)];
#pragma unroll
            for (int j = 0; j < 16; j++) {
#pragma unroll
                for (int u = 0; u < 4; u++) {
                    float4 kb = *(const float4*)&Ks[j * LQ2 + (c << 4) + (u << 2)];
                    s[j] = fmaf(qc[(u<<2)+0], kb.x, s[j]);
                    s[j] = fmaf(qc[(u<<2)+1], kb.y, s[j]);
                    s[j] = fmaf(qc[(u<<2)+2], kb.z, s[j]);
                    s[j] = fmaf(qc[(u<<2)+3], kb.w, s[j]);
                }
            }
        }

        // Private online softmax
        float mt = s[0];
#pragma unroll
        for (int j = 1; j < 16; j++) mt = fmaxf(mt, s[j]);
        const float mn   = fmaxf(mval, mt);
        const float corr = __expf(mval - mn);
        mval = mn;
        float ps = 0.f;
#pragma unroll
        for (int j = 0; j < 16; j++) { s[j] = __expf(s[j] - mn); ps += s[j]; }
        lval = lval * corr + ps;
#pragma unroll
        for (int e = 0; e < 64; e++) o[e] *= corr;

        // O += P @ V (V rows broadcast from smem)
#pragma unroll
        for (int j = 0; j < 16; j++) {
            const float pj = s[j];
#pragma unroll
            for (int e4 = 0; e4 < 16; e4++) {
                float4 vb = *(const float4*)&Vs[j * LQ2 + (e4 << 2)];
                o[(e4<<2)+0] = fmaf(pj, vb.x, o[(e4<<2)+0]);
                o[(e4<<2)+1] = fmaf(pj, vb.y, o[(e4<<2)+1]);
                o[(e4<<2)+2] = fmaf(pj, vb.z, o[(e4<<2)+2]);
                o[(e4<<2)+3] = fmaf(pj, vb.w, o[(e4<<2)+3]);
            }
        }
    }

    const float inv = 1.f / lval;
    float* cp = ctx + (b * 2048 + (qt << 7) + t) * 1024 + (h << 6);
#pragma unroll
    for (int e4 = 0; e4 < 16; e4++) {
        *(float4*)(cp + (e4 << 2)) =
            make_float4(o[(e4<<2)+0] * inv, o[(e4<<2)+1] * inv,
                        o[(e4<<2)+2] * inv, o[(e4<<2)+3] * inv);
    }
}

// ---------------------------------------------------------------------------
extern "C" void kernel_launch(void* const* d_in, const int* in_sizes, int n_in,
                              void* d_out, int out_size)
{
    const float* x  = (const float*)d_in[0];
    const float* Wq = (const float*)d_in[1];
    const float* Wk = (const float*)d_in[2];
    const float* Wv = (const float*)d_in[3];
    const float* Wo = (const float*)d_in[4];
    float* out = (float*)d_out;

    float* gq;  cudaGetSymbolAddress((void**)&gq, n_q);
    float* gk;  cudaGetSymbolAddress((void**)&gk, n_k);
    float* gv;  cudaGetSymbolAddress((void**)&gv, n_v);
    float* gc;  cudaGetSymbolAddress((void**)&gc, n_ctx);

    dim3 gg(8, 32);   // (N/128, M/128)
    gemm_k<<<gg, 256>>>(x,  Wq, gq);
    gemm_k<<<gg, 256>>>(x,  Wk, gk);
    gemm_k<<<gg, 256>>>(x,  Wv, gv);
    nrope<<<4096 * 16 * 32 / 256, 256>>>(gq, gk);
    fattn<<<dim3(16, 32), 128>>>(gq, gk, gv, gc);
    gemm_k<<<gg, 256>>>(gc, Wo, out);
}

// round 10
// speedup vs baseline: 20.9285x; 1.0382x over previous
#include <cuda_runtime.h>
#include <math.h>

// B=2, S=2048, D=1024, H=16, HD=64. Scratch: row-major [b*S+s][h*64+e].
__device__ float n_q[4096*1024];
__device__ float n_k[4096*1024];
__device__ float n_v[4096*1024];
__device__ float n_ctx[4096*1024];

// ---------------------------------------------------------------------------
// TF32 tensor-core GEMM: C[4096,1024] = A @ W^T (row-major).
// 128x128 tile, BK=16, 256 threads (8 warps: 4 m x 2 n; warp tile 32x64).
// Split-tf32: hi = rna_tf32(x), lo = x - hi (exact); D += ah*bh + ah*bl + al*bh
// (residual ~2^-22). hi/lo precomputed during smem staging.
// Smem k-major, LDP=132: fragment loads addr%32 = 4*(lane%4)+lane/4 -> conflict-free.
// grid.z selects (W, C) so QKV runs as one fused launch.
// ---------------------------------------------------------------------------
#define LDP 132

__device__ __forceinline__ void cvt_hl(float v, float& h, float& l) {
    unsigned u;
    asm("cvt.rna.tf32.f32 %0, %1;" : "=r"(u) : "f"(v));
    h = __uint_as_float(u);
    l = v - h;
}

__device__ __forceinline__ void mma8(float* d, const unsigned* a, unsigned b0, unsigned b1) {
    asm volatile(
        "mma.sync.aligned.m16n8k8.row.col.f32.tf32.tf32.f32 "
        "{%0,%1,%2,%3}, {%4,%5,%6,%7}, {%8,%9}, {%0,%1,%2,%3};"
        : "+f"(d[0]), "+f"(d[1]), "+f"(d[2]), "+f"(d[3])
        : "r"(a[0]), "r"(a[1]), "r"(a[2]), "r"(a[3]), "r"(b0), "r"(b1));
}

__global__ void __launch_bounds__(256) gemm_tf32(
    const float* __restrict__ A,
    const float* __restrict__ W0, const float* __restrict__ W1, const float* __restrict__ W2,
    float* __restrict__ C0, float* __restrict__ C1, float* __restrict__ C2)
{
    const float* W = (blockIdx.z == 0) ? W0 : (blockIdx.z == 1) ? W1 : W2;
    float*       C = (blockIdx.z == 0) ? C0 : (blockIdx.z == 1) ? C1 : C2;

    __shared__ float Ah[16 * LDP], Al[16 * LDP];
    __shared__ float Bh[16 * LDP], Bl[16 * LDP];

    const int t    = threadIdx.x;
    const int lane = t & 31;
    const int wid  = t >> 5;
    const int wm   = (wid & 3) << 5;    // warp row base: 0,32,64,96
    const int wn   = (wid >> 2) << 6;   // warp col base: 0,64
    const int m0   = blockIdx.y << 7;
    const int n0   = blockIdx.x << 7;

    const int row0 = t >> 2;            // loader: rows row0, row0+64
    const int kg   = (t & 3) << 2;      // loader: k-cols kg..kg+3

    const int lq = lane >> 2;           // groupID   (0..7)
    const int lr = lane & 3;            // id-in-group (0..3)

    float acc[2][8][4];
#pragma unroll
    for (int mt = 0; mt < 2; mt++)
#pragma unroll
        for (int nt = 0; nt < 8; nt++)
#pragma unroll
            for (int f = 0; f < 4; f++) acc[mt][nt][f] = 0.f;

    for (int k0 = 0; k0 < 1024; k0 += 16) {
        float4 a0v = *(const float4*)(A + (m0 + row0)      * 1024 + k0 + kg);
        float4 a1v = *(const float4*)(A + (m0 + row0 + 64) * 1024 + k0 + kg);
        float4 b0v = *(const float4*)(W + (n0 + row0)      * 1024 + k0 + kg);
        float4 b1v = *(const float4*)(W + (n0 + row0 + 64) * 1024 + k0 + kg);

        __syncthreads();   // previous iteration's smem reads complete

        float h, l;
        cvt_hl(a0v.x, h, l); Ah[(kg+0)*LDP + row0] = h;      Al[(kg+0)*LDP + row0] = l;
        cvt_hl(a0v.y, h, l); Ah[(kg+1)*LDP + row0] = h;      Al[(kg+1)*LDP + row0] = l;
        cvt_hl(a0v.z, h, l); Ah[(kg+2)*LDP + row0] = h;      Al[(kg+2)*LDP + row0] = l;
        cvt_hl(a0v.w, h, l); Ah[(kg+3)*LDP + row0] = h;      Al[(kg+3)*LDP + row0] = l;
        cvt_hl(a1v.x, h, l); Ah[(kg+0)*LDP + row0 + 64] = h; Al[(kg+0)*LDP + row0 + 64] = l;
        cvt_hl(a1v.y, h, l); Ah[(kg+1)*LDP + row0 + 64] = h; Al[(kg+1)*LDP + row0 + 64] = l;
        cvt_hl(a1v.z, h, l); Ah[(kg+2)*LDP + row0 + 64] = h; Al[(kg+2)*LDP + row0 + 64] = l;
        cvt_hl(a1v.w, h, l); Ah[(kg+3)*LDP + row0 + 64] = h; Al[(kg+3)*LDP + row0 + 64] = l;
        cvt_hl(b0v.x, h, l); Bh[(kg+0)*LDP + row0] = h;      Bl[(kg+0)*LDP + row0] = l;
        cvt_hl(b0v.y, h, l); Bh[(kg+1)*LDP + row0] = h;      Bl[(kg+1)*LDP + row0] = l;
        cvt_hl(b0v.z, h, l); Bh[(kg+2)*LDP + row0] = h;      Bl[(kg+2)*LDP + row0] = l;
        cvt_hl(b0v.w, h, l); Bh[(kg+3)*LDP + row0] = h;      Bl[(kg+3)*LDP + row0] = l;
        cvt_hl(b1v.x, h, l); Bh[(kg+0)*LDP + row0 + 64] = h; Bl[(kg+0)*LDP + row0 + 64] = l;
        cvt_hl(b1v.y, h, l); Bh[(kg+1)*LDP + row0 + 64] = h; Bl[(kg+1)*LDP + row0 + 64] = l;
        cvt_hl(b1v.z, h, l); Bh[(kg+2)*LDP + row0 + 64] = h; Bl[(kg+2)*LDP + row0 + 64] = l;
        cvt_hl(b1v.w, h, l); Bh[(kg+3)*LDP + row0 + 64] = h; Bl[(kg+3)*LDP + row0 + 64] = l;

        __syncthreads();   // tile ready

#pragma unroll
        for (int ks = 0; ks < 2; ks++) {
            const int kb = ks << 3;
            const int kk = kb + lr;     // this thread's k cols: kk, kk+4

            // A fragments (2 m16 tiles), hi and lo
            unsigned ah[2][4], al[2][4];
#pragma unroll
            for (int mt = 0; mt < 2; mt++) {
                const int r = wm + (mt << 4) + lq;
                ah[mt][0] = __float_as_uint(Ah[kk*LDP + r]);
                ah[mt][1] = __float_as_uint(Ah[kk*LDP + r + 8]);
                ah[mt][2] = __float_as_uint(Ah[(kk+4)*LDP + r]);
                ah[mt][3] = __float_as_uint(Ah[(kk+4)*LDP + r + 8]);
                al[mt][0] = __float_as_uint(Al[kk*LDP + r]);
                al[mt][1] = __float_as_uint(Al[kk*LDP + r + 8]);
                al[mt][2] = __float_as_uint(Al[(kk+4)*LDP + r]);
                al[mt][3] = __float_as_uint(Al[(kk+4)*LDP + r + 8]);
            }

#pragma unroll
            for (int nt = 0; nt < 8; nt++) {
                const int c = wn + (nt << 3) + lq;       // B col (= W row)
                const unsigned bh0 = __float_as_uint(Bh[kk*LDP + c]);
                const unsigned bh1 = __float_as_uint(Bh[(kk+4)*LDP + c]);
                const unsigned bl0 = __float_as_uint(Bl[kk*LDP + c]);
                const unsigned bl1 = __float_as_uint(Bl[(kk+4)*LDP + c]);
#pragma unroll
                for (int mt = 0; mt < 2; mt++) {
                    mma8(acc[mt][nt], ah[mt], bh0, bh1);
                    mma8(acc[mt][nt], ah[mt], bl0, bl1);
                    mma8(acc[mt][nt], al[mt], bh0, bh1);
                }
            }
        }
    }

    // Writeback: c0/c1 -> (row, 2*lr), (row, 2*lr+1); c2/c3 -> row+8
#pragma unroll
    for (int mt = 0; mt < 2; mt++)
#pragma unroll
        for (int nt = 0; nt < 8; nt++) {
            const int m = m0 + wm + (mt << 4) + lq;
            const int n = n0 + wn + (nt << 3) + (lr << 1);
            *(float2*)&C[m * 1024 + n]       = make_float2(acc[mt][nt][0], acc[mt][nt][1]);
            *(float2*)&C[(m + 8) * 1024 + n] = make_float2(acc[mt][nt][2], acc[mt][nt][3]);
        }
}

// ---------------------------------------------------------------------------
// RoPE — VERBATIM from the passing R8/R9 kernel. Do not touch.
// ---------------------------------------------------------------------------
__global__ void nrope(float* q, float* k)
{
    const int g = blockIdx.x * 256 + threadIdx.x;  // < 4096*16*32
    const int i = g & 31;
    const int h = (g >> 5) & 15;
    const int m = g >> 9;          // 0..4095
    const int s = m & 2047;
    const float freq = powf(10000.0f, -(float)i / 32.0f);
    const float ang  = (float)s * freq;
    const float c = cosf(ang), sn = sinf(ang);
    const int o = m * 1024 + h * 64 + i;
    float x1 = q[o], x2 = q[o + 32];
    q[o]      = x1 * c - x2 * sn;
    q[o + 32] = x2 * c + x1 * sn;
    x1 = k[o]; x2 = k[o + 32];
    k[o]      = x1 * c - x2 * sn;
    k[o + 32] = x2 * c + x1 * sn;
}

// ---------------------------------------------------------------------------
// Flash attention — VERBATIM from the passing R9 kernel. Do not touch.
// ---------------------------------------------------------------------------
#define LQ2 68

__global__ void __launch_bounds__(128) fattn(const float* __restrict__ q,
                                             const float* __restrict__ k,
                                             const float* __restrict__ v,
                                             float* __restrict__ ctx)
{
    __shared__ float Qs[128 * LQ2];
    __shared__ float Ks[16 * LQ2];
    __shared__ float Vs[16 * LQ2];

    const int t  = threadIdx.x;          // 0..127 = this thread's q-row in tile
    const int qt = blockIdx.x;           // 0..15
    const int bh = blockIdx.y;           // 0..31
    const int b  = bh >> 4, h = bh & 15;

    const float* qg = q + (b * 2048 + (qt << 7)) * 1024 + (h << 6);
    const float* kg = k + (b * 2048) * 1024 + (h << 6);
    const float* vg = v + (b * 2048) * 1024 + (h << 6);

#pragma unroll
    for (int p = 0; p < 16; p++) {
        const int idx = (p << 7) + t;
        const int r = idx >> 4, g4 = (idx & 15) << 2;
        float4 q4 = *(const float4*)(qg + r * 1024 + g4);
        q4.x *= 0.125f; q4.y *= 0.125f; q4.z *= 0.125f; q4.w *= 0.125f;
        *(float4*)&Qs[r * LQ2 + g4] = q4;
    }

    float o[64];
#pragma unroll
    for (int e = 0; e < 64; e++) o[e] = 0.f;
    float mval = -1e30f, lval = 0.f;

    for (int kt = 0; kt < 128; kt++) {
        __syncthreads();   // prev tile's Ks/Vs reads done; covers Qs on iter 0
#pragma unroll
        for (int p = 0; p < 2; p++) {
            const int idx = (p << 7) + t;
            const int r = idx >> 4, g4 = (idx & 15) << 2;
            *(float4*)&Ks[r * LQ2 + g4] = *(const float4*)(kg + ((kt << 4) + r) * 1024 + g4);
            *(float4*)&Vs[r * LQ2 + g4] = *(const float4*)(vg + ((kt << 4) + r) * 1024 + g4);
        }
        __syncthreads();

        float s[16];
#pragma unroll
        for (int j = 0; j < 16; j++) s[j] = 0.f;
#pragma unroll
        for (int c = 0; c < 4; c++) {        // d-chunks of 16
            float qc[16];
#pragma unroll
            for (int u = 0; u < 4; u++)
                *(float4*)&qc[u << 2] = *(const float4*)&Qs[t * LQ2 + (c << 4) + (u << 2)];
#pragma unroll
            for (int j = 0; j < 16; j++) {
#pragma unroll
                for (int u = 0; u < 4; u++) {
                    float4 kb = *(const float4*)&Ks[j * LQ2 + (c << 4) + (u << 2)];
                    s[j] = fmaf(qc[(u<<2)+0], kb.x, s[j]);
                    s[j] = fmaf(qc[(u<<2)+1], kb.y, s[j]);
                    s[j] = fmaf(qc[(u<<2)+2], kb.z, s[j]);
                    s[j] = fmaf(qc[(u<<2)+3], kb.w, s[j]);
                }
            }
        }

        float mt = s[0];
#pragma unroll
        for (int j = 1; j < 16; j++) mt = fmaxf(mt, s[j]);
        const float mn   = fmaxf(mval, mt);
        const float corr = __expf(mval - mn);
        mval = mn;
        float ps = 0.f;
#pragma unroll
        for (int j = 0; j < 16; j++) { s[j] = __expf(s[j] - mn); ps += s[j]; }
        lval = lval * corr + ps;
#pragma unroll
        for (int e = 0; e < 64; e++) o[e] *= corr;

#pragma unroll
        for (int j = 0; j < 16; j++) {
            const float pj = s[j];
#pragma unroll
            for (int e4 = 0; e4 < 16; e4++) {
                float4 vb = *(const float4*)&Vs[j * LQ2 + (e4 << 2)];
                o[(e4<<2)+0] = fmaf(pj, vb.x, o[(e4<<2)+0]);
                o[(e4<<2)+1] = fmaf(pj, vb.y, o[(e4<<2)+1]);
                o[(e4<<2)+2] = fmaf(pj, vb.z, o[(e4<<2)+2]);
                o[(e4<<2)+3] = fmaf(pj, vb.w, o[(e4<<2)+3]);
            }
        }
    }

    const float inv = 1.f / lval;
    float* cp = ctx + (b * 2048 + (qt << 7) + t) * 1024 + (h << 6);
#pragma unroll
    for (int e4 = 0; e4 < 16; e4++) {
        *(float4*)(cp + (e4 << 2)) =
            make_float4(o[(e4<<2)+0] * inv, o[(e4<<2)+1] * inv,
                        o[(e4<<2)+2] * inv, o[(e4<<2)+3] * inv);
    }
}

// ---------------------------------------------------------------------------
extern "C" void kernel_launch(void* const* d_in, const int* in_sizes, int n_in,
                              void* d_out, int out_size)
{
    const float* x  = (const float*)d_in[0];
    const float* Wq = (const float*)d_in[1];
    const float* Wk = (const float*)d_in[2];
    const float* Wv = (const float*)d_in[3];
    const float* Wo = (const float*)d_in[4];
    float* out = (float*)d_out;

    float* gq;  cudaGetSymbolAddress((void**)&gq, n_q);
    float* gk;  cudaGetSymbolAddress((void**)&gk, n_k);
    float* gv;  cudaGetSymbolAddress((void**)&gv, n_v);
    float* gc;  cudaGetSymbolAddress((void**)&gc, n_ctx);

    gemm_tf32<<<dim3(8, 32, 3), 256>>>(x, Wq, Wk, Wv, gq, gk, gv);
    nrope<<<4096 * 16 * 32 / 256, 256>>>(gq, gk);
    fattn<<<dim3(16, 32), 128>>>(gq, gk, gv, gc);
    gemm_tf32<<<dim3(8, 32, 1), 256>>>(gc, Wo, Wo, Wo, out, out, out);
}

// round 12
// speedup vs baseline: 24.7378x; 1.1820x over previous
#include <cuda_runtime.h>
#include <math.h>

// B=2, S=2048, D=1024, H=16, HD=64. Scratch row-major [b*S+s][h*64+e],
// plus per-head transposed q/k: [bh][d][s].
__device__ float n_q[4096*1024];
__device__ float n_k[4096*1024];
__device__ float n_v[4096*1024];
__device__ float n_ctx[4096*1024];
__device__ float n_qT[32*64*2048];
__device__ float n_kT[32*64*2048];

// ---------------------------------------------------------------------------
// Split-tf32 helpers (verified in R10: rel_err 2.9e-5)
// ---------------------------------------------------------------------------
__device__ __forceinline__ void cvt_hl(float v, float& h, float& l) {
    unsigned u;
    asm("cvt.rna.tf32.f32 %0, %1;" : "=r"(u) : "f"(v));
    h = __uint_as_float(u);
    l = v - h;
}

__device__ __forceinline__ void mma8(float* d, const unsigned* a, unsigned b0, unsigned b1) {
    asm volatile(
        "mma.sync.aligned.m16n8k8.row.col.f32.tf32.tf32.f32 "
        "{%0,%1,%2,%3}, {%4,%5,%6,%7}, {%8,%9}, {%0,%1,%2,%3};"
        : "+f"(d[0]), "+f"(d[1]), "+f"(d[2]), "+f"(d[3])
        : "r"(a[0]), "r"(a[1]), "r"(a[2]), "r"(a[3]), "r"(b0), "r"(b1));
}

// ---------------------------------------------------------------------------
// TF32 GEMM — VERBATIM from passing R10. C = A @ W^T.
// ---------------------------------------------------------------------------
#define LDP 132

__global__ void __launch_bounds__(256) gemm_tf32(
    const float* __restrict__ A,
    const float* __restrict__ W0, const float* __restrict__ W1, const float* __restrict__ W2,
    float* __restrict__ C0, float* __restrict__ C1, float* __restrict__ C2)
{
    const float* W = (blockIdx.z == 0) ? W0 : (blockIdx.z == 1) ? W1 : W2;
    float*       C = (blockIdx.z == 0) ? C0 : (blockIdx.z == 1) ? C1 : C2;

    __shared__ float Ah[16 * LDP], Al[16 * LDP];
    __shared__ float Bh[16 * LDP], Bl[16 * LDP];

    const int t    = threadIdx.x;
    const int lane = t & 31;
    const int wid  = t >> 5;
    const int wm   = (wid & 3) << 5;
    const int wn   = (wid >> 2) << 6;
    const int m0   = blockIdx.y << 7;
    const int n0   = blockIdx.x << 7;

    const int row0 = t >> 2;
    const int kg   = (t & 3) << 2;

    const int lq = lane >> 2;
    const int lr = lane & 3;

    float acc[2][8][4];
#pragma unroll
    for (int mt = 0; mt < 2; mt++)
#pragma unroll
        for (int nt = 0; nt < 8; nt++)
#pragma unroll
            for (int f = 0; f < 4; f++) acc[mt][nt][f] = 0.f;

    for (int k0 = 0; k0 < 1024; k0 += 16) {
        float4 a0v = *(const float4*)(A + (m0 + row0)      * 1024 + k0 + kg);
        float4 a1v = *(const float4*)(A + (m0 + row0 + 64) * 1024 + k0 + kg);
        float4 b0v = *(const float4*)(W + (n0 + row0)      * 1024 + k0 + kg);
        float4 b1v = *(const float4*)(W + (n0 + row0 + 64) * 1024 + k0 + kg);

        __syncthreads();

        float h, l;
        cvt_hl(a0v.x, h, l); Ah[(kg+0)*LDP + row0] = h;      Al[(kg+0)*LDP + row0] = l;
        cvt_hl(a0v.y, h, l); Ah[(kg+1)*LDP + row0] = h;      Al[(kg+1)*LDP + row0] = l;
        cvt_hl(a0v.z, h, l); Ah[(kg+2)*LDP + row0] = h;      Al[(kg+2)*LDP + row0] = l;
        cvt_hl(a0v.w, h, l); Ah[(kg+3)*LDP + row0] = h;      Al[(kg+3)*LDP + row0] = l;
        cvt_hl(a1v.x, h, l); Ah[(kg+0)*LDP + row0 + 64] = h; Al[(kg+0)*LDP + row0 + 64] = l;
        cvt_hl(a1v.y, h, l); Ah[(kg+1)*LDP + row0 + 64] = h; Al[(kg+1)*LDP + row0 + 64] = l;
        cvt_hl(a1v.z, h, l); Ah[(kg+2)*LDP + row0 + 64] = h; Al[(kg+2)*LDP + row0 + 64] = l;
        cvt_hl(a1v.w, h, l); Ah[(kg+3)*LDP + row0 + 64] = h; Al[(kg+3)*LDP + row0 + 64] = l;
        cvt_hl(b0v.x, h, l); Bh[(kg+0)*LDP + row0] = h;      Bl[(kg+0)*LDP + row0] = l;
        cvt_hl(b0v.y, h, l); Bh[(kg+1)*LDP + row0] = h;      Bl[(kg+1)*LDP + row0] = l;
        cvt_hl(b0v.z, h, l); Bh[(kg+2)*LDP + row0] = h;      Bl[(kg+2)*LDP + row0] = l;
        cvt_hl(b0v.w, h, l); Bh[(kg+3)*LDP + row0] = h;      Bl[(kg+3)*LDP + row0] = l;
        cvt_hl(b1v.x, h, l); Bh[(kg+0)*LDP + row0 + 64] = h; Bl[(kg+0)*LDP + row0 + 64] = l;
        cvt_hl(b1v.y, h, l); Bh[(kg+1)*LDP + row0 + 64] = h; Bl[(kg+1)*LDP + row0 + 64] = l;
        cvt_hl(b1v.z, h, l); Bh[(kg+2)*LDP + row0 + 64] = h; Bl[(kg+2)*LDP + row0 + 64] = l;
        cvt_hl(b1v.w, h, l); Bh[(kg+3)*LDP + row0 + 64] = h; Bl[(kg+3)*LDP + row0 + 64] = l;

        __syncthreads();

#pragma unroll
        for (int ks = 0; ks < 2; ks++) {
            const int kk = (ks << 3) + lr;

            unsigned ah[2][4], al[2][4];
#pragma unroll
            for (int mt = 0; mt < 2; mt++) {
                const int r = wm + (mt << 4) + lq;
                ah[mt][0] = __float_as_uint(Ah[kk*LDP + r]);
                ah[mt][1] = __float_as_uint(Ah[kk*LDP + r + 8]);
                ah[mt][2] = __float_as_uint(Ah[(kk+4)*LDP + r]);
                ah[mt][3] = __float_as_uint(Ah[(kk+4)*LDP + r + 8]);
                al[mt][0] = __float_as_uint(Al[kk*LDP + r]);
                al[mt][1] = __float_as_uint(Al[kk*LDP + r + 8]);
                al[mt][2] = __float_as_uint(Al[(kk+4)*LDP + r]);
                al[mt][3] = __float_as_uint(Al[(kk+4)*LDP + r + 8]);
            }

#pragma unroll
            for (int nt = 0; nt < 8; nt++) {
                const int c = wn + (nt << 3) + lq;
                const unsigned bh0 = __float_as_uint(Bh[kk*LDP + c]);
                const unsigned bh1 = __float_as_uint(Bh[(kk+4)*LDP + c]);
                const unsigned bl0 = __float_as_uint(Bl[kk*LDP + c]);
                const unsigned bl1 = __float_as_uint(Bl[(kk+4)*LDP + c]);
#pragma unroll
                for (int mt = 0; mt < 2; mt++) {
                    mma8(acc[mt][nt], ah[mt], bh0, bh1);
                    mma8(acc[mt][nt], ah[mt], bl0, bl1);
                    mma8(acc[mt][nt], al[mt], bh0, bh1);
                }
            }
        }
    }

#pragma unroll
    for (int mt = 0; mt < 2; mt++)
#pragma unroll
        for (int nt = 0; nt < 8; nt++) {
            const int m = m0 + wm + (mt << 4) + lq;
            const int n = n0 + wn + (nt << 3) + (lr << 1);
            *(float2*)&C[m * 1024 + n]       = make_float2(acc[mt][nt][0], acc[mt][nt][1]);
            *(float2*)&C[(m + 8) * 1024 + n] = make_float2(acc[mt][nt][2], acc[mt][nt][3]);
        }
}

// ---------------------------------------------------------------------------
// RoPE — VERBATIM from passing kernels.
// ---------------------------------------------------------------------------
__global__ void nrope(float* q, float* k)
{
    const int g = blockIdx.x * 256 + threadIdx.x;
    const int i = g & 31;
    const int h = (g >> 5) & 15;
    const int m = g >> 9;
    const int s = m & 2047;
    const float freq = powf(10000.0f, -(float)i / 32.0f);
    const float ang  = (float)s * freq;
    const float c = cosf(ang), sn = sinf(ang);
    const int o = m * 1024 + h * 64 + i;
    float x1 = q[o], x2 = q[o + 32];
    q[o]      = x1 * c - x2 * sn;
    q[o + 32] = x2 * c + x1 * sn;
    x1 = k[o]; x2 = k[o + 32];
    k[o]      = x1 * c - x2 * sn;
    k[o + 32] = x2 * c + x1 * sn;
}

// ---------------------------------------------------------------------------
// Per-head transpose: q,k [b*S+s][h*64+d] -> [bh][d][s]. Smem-tiled 64x64.
// Odd stride 65 keeps both phases <=2-way conflicted.
// ---------------------------------------------------------------------------
__global__ void __launch_bounds__(256) trans_hd(const float* __restrict__ q,
                                                const float* __restrict__ k,
                                                float* __restrict__ qT,
                                                float* __restrict__ kT)
{
    __shared__ float Tq[64 * 65];
    __shared__ float Tk[64 * 65];
    const int t  = threadIdx.x;
    const int s0 = blockIdx.x << 6;
    const int bh = blockIdx.y;
    const int b  = bh >> 4, h = bh & 15;

#pragma unroll
    for (int p = 0; p < 4; p++) {
        const int idx = (p << 8) + t;
        const int sl = idx >> 4, d4 = (idx & 15) << 2;
        const float4 vq = *(const float4*)(q + (size_t)(b*2048 + s0 + sl)*1024 + (h<<6) + d4);
        const float4 vk = *(const float4*)(k + (size_t)(b*2048 + s0 + sl)*1024 + (h<<6) + d4);
        Tq[sl*65 + d4+0] = vq.x; Tq[sl*65 + d4+1] = vq.y;
        Tq[sl*65 + d4+2] = vq.z; Tq[sl*65 + d4+3] = vq.w;
        Tk[sl*65 + d4+0] = vk.x; Tk[sl*65 + d4+1] = vk.y;
        Tk[sl*65 + d4+2] = vk.z; Tk[sl*65 + d4+3] = vk.w;
    }
    __syncthreads();
#pragma unroll
    for (int p = 0; p < 4; p++) {
        const int idx = (p << 8) + t;
        const int d = idx >> 4, s4 = (idx & 15) << 2;
        float4 oq, ok;
        oq.x = Tq[(s4+0)*65 + d]; oq.y = Tq[(s4+1)*65 + d];
        oq.z = Tq[(s4+2)*65 + d]; oq.w = Tq[(s4+3)*65 + d];
        ok.x = Tk[(s4+0)*65 + d]; ok.y = Tk[(s4+1)*65 + d];
        ok.z = Tk[(s4+2)*65 + d]; ok.w = Tk[(s4+3)*65 + d];
        *(float4*)(qT + (size_t)bh*131072 + d*2048 + s0 + s4) = oq;
        *(float4*)(kT + (size_t)bh*131072 + d*2048 + s0 + s4) = ok;
    }
}

// ---------------------------------------------------------------------------
// Tensor-core flash attention. Block = (qt: 64 q-rows, bh). 256 thr, 8 warps.
// Smem stride 68 (== 4 mod 32: fragment loads are the R10-verified permutation).
// Per 64-key tile: QK mma (split-tf32, 3 passes) -> S^T to smem -> softmax
// thread-per-row (NO shuffles) -> PV mma (split, 3 passes) with in-register
// O-fragment correction.
// ---------------------------------------------------------------------------
#define LA 68
#define ATT_SMEM ((9*4352 + 128) * 4)

__global__ void __launch_bounds__(256) attn_mma()
{
    extern __shared__ float sm[];
    float* Qh = sm;
    float* Ql = sm + 1*4352;
    float* Kh = sm + 2*4352;
    float* Kl = sm + 3*4352;
    float* Vh = sm + 4*4352;
    float* Vl = sm + 5*4352;
    float* Ph = sm + 6*4352;
    float* Pl = sm + 7*4352;
    float* Ss = sm + 8*4352;
    float* cS = sm + 9*4352;        // corr[64]
    float* lS = cS + 64;            // linv[64]

    const int t    = threadIdx.x;
    const int lane = t & 31, wid = t >> 5;
    const int lq   = lane >> 2, lr = lane & 3;
    const int wm   = (wid & 3) << 4;     // q-tile base
    const int wn   = (wid >> 2) << 5;    // key/e base: 0 or 32
    const int qt   = blockIdx.x;         // 0..31
    const int bh   = blockIdx.y;
    const int b    = bh >> 4, h = bh & 15;

    const float* qTp = n_qT + (size_t)bh*131072 + (qt << 6);
    const float* kTp = n_kT + (size_t)bh*131072;
    const float* vp  = n_v + (size_t)(b*2048)*1024 + (h << 6);

    // Stage Q d-major, scaled by 1/8 (exact), split h/l. Coalesced + conflict-free.
#pragma unroll
    for (int p = 0; p < 4; p++) {
        const int idx = (p << 8) + t;
        const int d = idx >> 4, q4 = (idx & 15) << 2;
        float4 v = *(const float4*)(qTp + d*2048 + q4);
        float h0,l0,h1,l1,h2,l2,h3,l3;
        cvt_hl(v.x*0.125f,h0,l0); cvt_hl(v.y*0.125f,h1,l1);
        cvt_hl(v.z*0.125f,h2,l2); cvt_hl(v.w*0.125f,h3,l3);
        *(float4*)&Qh[d*LA + q4] = make_float4(h0,h1,h2,h3);
        *(float4*)&Ql[d*LA + q4] = make_float4(l0,l1,l2,l3);
    }

    float acc[4][4];
#pragma unroll
    for (int nt = 0; nt < 4; nt++)
#pragma unroll
        for (int f = 0; f < 4; f++) acc[nt][f] = 0.f;
    float m_r = -1e30f, l_r = 0.f;

    for (int kt = 0; kt < 32; kt++) {
        __syncthreads();   // prev PV finished reading V/P; staging may overwrite

        // Stage K (d-major from kT) and V (natural), split h/l
#pragma unroll
        for (int p = 0; p < 4; p++) {
            const int idx = (p << 8) + t;
            const int d = idx >> 4, c4 = (idx & 15) << 2;
            float4 v = *(const float4*)(kTp + d*2048 + (kt << 6) + c4);
            float h0,l0,h1,l1,h2,l2,h3,l3;
            cvt_hl(v.x,h0,l0); cvt_hl(v.y,h1,l1); cvt_hl(v.z,h2,l2); cvt_hl(v.w,h3,l3);
            *(float4*)&Kh[d*LA + c4] = make_float4(h0,h1,h2,h3);
            *(float4*)&Kl[d*LA + c4] = make_float4(l0,l1,l2,l3);
        }
#pragma unroll
        for (int p = 0; p < 4; p++) {
            const int idx = (p << 8) + t;
            const int r = idx >> 4, e4 = (idx & 15) << 2;
            float4 v = *(const float4*)(vp + (size_t)((kt << 6) + r)*1024 + e4);
            float h0,l0,h1,l1,h2,l2,h3,l3;
            cvt_hl(v.x,h0,l0); cvt_hl(v.y,h1,l1); cvt_hl(v.z,h2,l2); cvt_hl(v.w,h3,l3);
            *(float4*)&Vh[r*LA + e4] = make_float4(h0,h1,h2,h3);
            *(float4*)&Vl[r*LA + e4] = make_float4(l0,l1,l2,l3);
        }
        __syncthreads();

        // ---- QK: S[64q x 64key], warp does 16q x 32key ----
        float sacc[4][4];
#pragma unroll
        for (int nt = 0; nt < 4; nt++)
#pragma unroll
            for (int f = 0; f < 4; f++) sacc[nt][f] = 0.f;

#pragma unroll
        for (int ks = 0; ks < 8; ks++) {
            const int kk = (ks << 3) + lr;          // d index
            const int r  = wm + lq;
            unsigned ah[4], al[4];
            ah[0] = __float_as_uint(Qh[kk*LA + r]);
            ah[1] = __float_as_uint(Qh[kk*LA + r + 8]);
            ah[2] = __float_as_uint(Qh[(kk+4)*LA + r]);
            ah[3] = __float_as_uint(Qh[(kk+4)*LA + r + 8]);
            al[0] = __float_as_uint(Ql[kk*LA + r]);
            al[1] = __float_as_uint(Ql[kk*LA + r + 8]);
            al[2] = __float_as_uint(Ql[(kk+4)*LA + r]);
            al[3] = __float_as_uint(Ql[(kk+4)*LA + r + 8]);
#pragma unroll
            for (int nt = 0; nt < 4; nt++) {
                const int c = wn + (nt << 3) + lq;  // key col
                const unsigned bh0 = __float_as_uint(Kh[kk*LA + c]);
                const unsigned bh1 = __float_as_uint(Kh[(kk+4)*LA + c]);
                const unsigned bl0 = __float_as_uint(Kl[kk*LA + c]);
                const unsigned bl1 = __float_as_uint(Kl[(kk+4)*LA + c]);
                mma8(sacc[nt], ah, bh0, bh1);
                mma8(sacc[nt], ah, bl0, bl1);
                mma8(sacc[nt], al, bh0, bh1);
            }
        }

        // Write S transposed: Ss[key][q] (banks 8*lr+lq: perfect permutation)
#pragma unroll
        for (int nt = 0; nt < 4; nt++) {
            const int cb = wn + (nt << 3) + (lr << 1);
            const int r  = wm + lq;
            Ss[(cb+0)*LA + r]     = sacc[nt][0];
            Ss[(cb+1)*LA + r]     = sacc[nt][1];
            Ss[(cb+0)*LA + r + 8] = sacc[nt][2];
            Ss[(cb+1)*LA + r + 8] = sacc[nt][3];
        }
        __syncthreads();

        // ---- Softmax: thread t<64 owns q-row t (private state, no shuffles) ----
        if (t < 64) {
            float smax = -1e30f;
#pragma unroll
            for (int j = 0; j < 64; j++)
                smax = fmaxf(smax, Ss[j*LA + t]);
            const float mn   = fmaxf(m_r, smax);
            const float corr = __expf(m_r - mn);
            m_r = mn;
            float sum = 0.f;
#pragma unroll
            for (int j = 0; j < 64; j++) {
                const float p = __expf(Ss[j*LA + t] - mn);
                float ph, pl;
                cvt_hl(p, ph, pl);
                Ph[j*LA + t] = ph;
                Pl[j*LA + t] = pl;
                sum += p;
            }
            l_r = l_r * corr + sum;
            cS[t] = corr;
        }
        __syncthreads();

        // ---- PV: O[64q x 64e] += P @ V, warp does 16q x 32e ----
        {
            const float c0 = cS[wm + lq], c1 = cS[wm + lq + 8];
#pragma unroll
            for (int nt = 0; nt < 4; nt++) {
                acc[nt][0] *= c0; acc[nt][1] *= c0;
                acc[nt][2] *= c1; acc[nt][3] *= c1;
            }
#pragma unroll
            for (int ks = 0; ks < 8; ks++) {
                const int kk = (ks << 3) + lr;      // key index
                const int r  = wm + lq;
                unsigned ah[4], al[4];
                ah[0] = __float_as_uint(Ph[kk*LA + r]);
                ah[1] = __float_as_uint(Ph[kk*LA + r + 8]);
                ah[2] = __float_as_uint(Ph[(kk+4)*LA + r]);
                ah[3] = __float_as_uint(Ph[(kk+4)*LA + r + 8]);
                al[0] = __float_as_uint(Pl[kk*LA + r]);
                al[1] = __float_as_uint(Pl[kk*LA + r + 8]);
                al[2] = __float_as_uint(Pl[(kk+4)*LA + r]);
                al[3] = __float_as_uint(Pl[(kk+4)*LA + r + 8]);
#pragma unroll
                for (int nt = 0; nt < 4; nt++) {
                    const int c = wn + (nt << 3) + lq;   // e col
                    const unsigned bh0 = __float_as_uint(Vh[kk*LA + c]);
                    const unsigned bh1 = __float_as_uint(Vh[(kk+4)*LA + c]);
                    const unsigned bl0 = __float_as_uint(Vl[kk*LA + c]);
                    const unsigned bl1 = __float_as_uint(Vl[(kk+4)*LA + c]);
                    mma8(acc[nt], ah, bh0, bh1);
                    mma8(acc[nt], ah, bl0, bl1);
                    mma8(acc[nt], al, bh0, bh1);
                }
            }
        }
    }

    if (t < 64) lS[t] = 1.f / l_r;
    __syncthreads();

    const float i0 = lS[wm + lq], i1 = lS[wm + lq + 8];
#pragma unroll
    for (int nt = 0; nt < 4; nt++) {
        const int q0 = (qt << 6) + wm + lq;
        const int e  = wn + (nt << 3) + (lr << 1);
        const size_t base = (size_t)(b*2048 + q0)*1024 + (h << 6) + e;
        *(float2*)&n_ctx[base]           = make_float2(acc[nt][0]*i0, acc[nt][1]*i0);
        *(float2*)&n_ctx[base + 8*1024]  = make_float2(acc[nt][2]*i1, acc[nt][3]*i1);
    }
}

// ---------------------------------------------------------------------------
extern "C" void kernel_launch(void* const* d_in, const int* in_sizes, int n_in,
                              void* d_out, int out_size)
{
    const float* x  = (const float*)d_in[0];
    const float* Wq = (const float*)d_in[1];
    const float* Wk = (const float*)d_in[2];
    const float* Wv = (const float*)d_in[3];
    const float* Wo = (const float*)d_in[4];
    float* out = (float*)d_out;

    float* gq;  cudaGetSymbolAddress((void**)&gq, n_q);
    float* gk;  cudaGetSymbolAddress((void**)&gk, n_k);
    float* gv;  cudaGetSymbolAddress((void**)&gv, n_v);
    float* gc;  cudaGetSymbolAddress((void**)&gc, n_ctx);
    float* gqT; cudaGetSymbolAddress((void**)&gqT, n_qT);
    float* gkT; cudaGetSymbolAddress((void**)&gkT, n_kT);

    cudaFuncSetAttribute(attn_mma, cudaFuncAttributeMaxDynamicSharedMemorySize, ATT_SMEM);

    gemm_tf32<<<dim3(8, 32, 3), 256>>>(x, Wq, Wk, Wv, gq, gk, gv);
    nrope<<<4096 * 16 * 32 / 256, 256>>>(gq, gk);
    trans_hd<<<dim3(32, 32), 256>>>(gq, gk, gqT, gkT);
    attn_mma<<<dim3(32, 32), 256, ATT_SMEM>>>();
    gemm_tf32<<<dim3(8, 32, 1), 256>>>(gc, Wo, Wo, Wo, out, out, out);
}

// round 13
// speedup vs baseline: 32.4377x; 1.3113x over previous
#include <cuda_runtime.h>
#include <math.h>

// B=2, S=2048, D=1024, H=16, HD=64. Scratch row-major [b*S+s][h*64+e],
// plus per-head transposed q/k: [bh][d][s].
__device__ float n_q[4096*1024];
__device__ float n_k[4096*1024];
__device__ float n_v[4096*1024];
__device__ float n_ctx[4096*1024];
__device__ float n_qT[32*64*2048];
__device__ float n_kT[32*64*2048];

// ---------------------------------------------------------------------------
// Split-tf32 helpers (verified R10/R12). hi/lo recomputed at fragment-load
// time: bit-identical to storing split arrays, half the smem + LDS.
// ---------------------------------------------------------------------------
__device__ __forceinline__ void cvt_hl(float v, float& h, float& l) {
    unsigned u;
    asm("cvt.rna.tf32.f32 %0, %1;" : "=r"(u) : "f"(v));
    h = __uint_as_float(u);
    l = v - h;
}

__device__ __forceinline__ void mma8(float* d, const unsigned* a, unsigned b0, unsigned b1) {
    asm volatile(
        "mma.sync.aligned.m16n8k8.row.col.f32.tf32.tf32.f32 "
        "{%0,%1,%2,%3}, {%4,%5,%6,%7}, {%8,%9}, {%0,%1,%2,%3};"
        : "+f"(d[0]), "+f"(d[1]), "+f"(d[2]), "+f"(d[3])
        : "r"(a[0]), "r"(a[1]), "r"(a[2]), "r"(a[3]), "r"(b0), "r"(b1));
}

// ---------------------------------------------------------------------------
// TF32 GEMM, single fp32 smem buffers (split at fragment load).
// C = A @ W^T. Same tiling/fragment mapping as passing R10/R12.
// ---------------------------------------------------------------------------
#define LDP 132

__global__ void __launch_bounds__(256) gemm_tf32(
    const float* __restrict__ A,
    const float* __restrict__ W0, const float* __restrict__ W1, const float* __restrict__ W2,
    float* __restrict__ C0, float* __restrict__ C1, float* __restrict__ C2)
{
    const float* W = (blockIdx.z == 0) ? W0 : (blockIdx.z == 1) ? W1 : W2;
    float*       C = (blockIdx.z == 0) ? C0 : (blockIdx.z == 1) ? C1 : C2;

    __shared__ float As[16 * LDP];
    __shared__ float Bs[16 * LDP];

    const int t    = threadIdx.x;
    const int lane = t & 31;
    const int wid  = t >> 5;
    const int wm   = (wid & 3) << 5;
    const int wn   = (wid >> 2) << 6;
    const int m0   = blockIdx.y << 7;
    const int n0   = blockIdx.x << 7;

    const int row0 = t >> 2;
    const int kg   = (t & 3) << 2;

    const int lq = lane >> 2;
    const int lr = lane & 3;

    float acc[2][8][4];
#pragma unroll
    for (int mt = 0; mt < 2; mt++)
#pragma unroll
        for (int nt = 0; nt < 8; nt++)
#pragma unroll
            for (int f = 0; f < 4; f++) acc[mt][nt][f] = 0.f;

    for (int k0 = 0; k0 < 1024; k0 += 16) {
        float4 a0v = *(const float4*)(A + (m0 + row0)      * 1024 + k0 + kg);
        float4 a1v = *(const float4*)(A + (m0 + row0 + 64) * 1024 + k0 + kg);
        float4 b0v = *(const float4*)(W + (n0 + row0)      * 1024 + k0 + kg);
        float4 b1v = *(const float4*)(W + (n0 + row0 + 64) * 1024 + k0 + kg);

        __syncthreads();

        As[(kg+0)*LDP + row0] = a0v.x;
        As[(kg+1)*LDP + row0] = a0v.y;
        As[(kg+2)*LDP + row0] = a0v.z;
        As[(kg+3)*LDP + row0] = a0v.w;
        As[(kg+0)*LDP + row0 + 64] = a1v.x;
        As[(kg+1)*LDP + row0 + 64] = a1v.y;
        As[(kg+2)*LDP + row0 + 64] = a1v.z;
        As[(kg+3)*LDP + row0 + 64] = a1v.w;
        Bs[(kg+0)*LDP + row0] = b0v.x;
        Bs[(kg+1)*LDP + row0] = b0v.y;
        Bs[(kg+2)*LDP + row0] = b0v.z;
        Bs[(kg+3)*LDP + row0] = b0v.w;
        Bs[(kg+0)*LDP + row0 + 64] = b1v.x;
        Bs[(kg+1)*LDP + row0 + 64] = b1v.y;
        Bs[(kg+2)*LDP + row0 + 64] = b1v.z;
        Bs[(kg+3)*LDP + row0 + 64] = b1v.w;

        __syncthreads();

#pragma unroll
        for (int ks = 0; ks < 2; ks++) {
            const int kk = (ks << 3) + lr;

            unsigned ah[2][4], al[2][4];
#pragma unroll
            for (int mt = 0; mt < 2; mt++) {
                const int r = wm + (mt << 4) + lq;
                float h, l;
                cvt_hl(As[kk*LDP + r],         h, l); ah[mt][0]=__float_as_uint(h); al[mt][0]=__float_as_uint(l);
                cvt_hl(As[kk*LDP + r + 8],     h, l); ah[mt][1]=__float_as_uint(h); al[mt][1]=__float_as_uint(l);
                cvt_hl(As[(kk+4)*LDP + r],     h, l); ah[mt][2]=__float_as_uint(h); al[mt][2]=__float_as_uint(l);
                cvt_hl(As[(kk+4)*LDP + r + 8], h, l); ah[mt][3]=__float_as_uint(h); al[mt][3]=__float_as_uint(l);
            }

#pragma unroll
            for (int nt = 0; nt < 8; nt++) {
                const int c = wn + (nt << 3) + lq;
                float bh0, bl0, bh1, bl1;
                cvt_hl(Bs[kk*LDP + c],     bh0, bl0);
                cvt_hl(Bs[(kk+4)*LDP + c], bh1, bl1);
                const unsigned ubh0 = __float_as_uint(bh0), ubh1 = __float_as_uint(bh1);
                const unsigned ubl0 = __float_as_uint(bl0), ubl1 = __float_as_uint(bl1);
#pragma unroll
                for (int mt = 0; mt < 2; mt++) {
                    mma8(acc[mt][nt], ah[mt], ubh0, ubh1);
                    mma8(acc[mt][nt], ah[mt], ubl0, ubl1);
                    mma8(acc[mt][nt], al[mt], ubh0, ubh1);
                }
            }
        }
    }

#pragma unroll
    for (int mt = 0; mt < 2; mt++)
#pragma unroll
        for (int nt = 0; nt < 8; nt++) {
            const int m = m0 + wm + (mt << 4) + lq;
            const int n = n0 + wn + (nt << 3) + (lr << 1);
            *(float2*)&C[m * 1024 + n]       = make_float2(acc[mt][nt][0], acc[mt][nt][1]);
            *(float2*)&C[(m + 8) * 1024 + n] = make_float2(acc[mt][nt][2], acc[mt][nt][3]);
        }
}

// ---------------------------------------------------------------------------
// RoPE — VERBATIM from passing kernels.
// ---------------------------------------------------------------------------
__global__ void nrope(float* q, float* k)
{
    const int g = blockIdx.x * 256 + threadIdx.x;
    const int i = g & 31;
    const int h = (g >> 5) & 15;
    const int m = g >> 9;
    const int s = m & 2047;
    const float freq = powf(10000.0f, -(float)i / 32.0f);
    const float ang  = (float)s * freq;
    const float c = cosf(ang), sn = sinf(ang);
    const int o = m * 1024 + h * 64 + i;
    float x1 = q[o], x2 = q[o + 32];
    q[o]      = x1 * c - x2 * sn;
    q[o + 32] = x2 * c + x1 * sn;
    x1 = k[o]; x2 = k[o + 32];
    k[o]      = x1 * c - x2 * sn;
    k[o + 32] = x2 * c + x1 * sn;
}

// ---------------------------------------------------------------------------
// Per-head transpose — VERBATIM from passing R12.
// ---------------------------------------------------------------------------
__global__ void __launch_bounds__(256) trans_hd(const float* __restrict__ q,
                                                const float* __restrict__ k,
                                                float* __restrict__ qT,
                                                float* __restrict__ kT)
{
    __shared__ float Tq[64 * 65];
    __shared__ float Tk[64 * 65];
    const int t  = threadIdx.x;
    const int s0 = blockIdx.x << 6;
    const int bh = blockIdx.y;
    const int b  = bh >> 4, h = bh & 15;

#pragma unroll
    for (int p = 0; p < 4; p++) {
        const int idx = (p << 8) + t;
        const int sl = idx >> 4, d4 = (idx & 15) << 2;
        const float4 vq = *(const float4*)(q + (size_t)(b*2048 + s0 + sl)*1024 + (h<<6) + d4);
        const float4 vk = *(const float4*)(k + (size_t)(b*2048 + s0 + sl)*1024 + (h<<6) + d4);
        Tq[sl*65 + d4+0] = vq.x; Tq[sl*65 + d4+1] = vq.y;
        Tq[sl*65 + d4+2] = vq.z; Tq[sl*65 + d4+3] = vq.w;
        Tk[sl*65 + d4+0] = vk.x; Tk[sl*65 + d4+1] = vk.y;
        Tk[sl*65 + d4+2] = vk.z; Tk[sl*65 + d4+3] = vk.w;
    }
    __syncthreads();
#pragma unroll
    for (int p = 0; p < 4; p++) {
        const int idx = (p << 8) + t;
        const int d = idx >> 4, s4 = (idx & 15) << 2;
        float4 oq, ok;
        oq.x = Tq[(s4+0)*65 + d]; oq.y = Tq[(s4+1)*65 + d];
        oq.z = Tq[(s4+2)*65 + d]; oq.w = Tq[(s4+3)*65 + d];
        ok.x = Tk[(s4+0)*65 + d]; ok.y = Tk[(s4+1)*65 + d];
        ok.z = Tk[(s4+2)*65 + d]; ok.w = Tk[(s4+3)*65 + d];
        *(float4*)(qT + (size_t)bh*131072 + d*2048 + s0 + s4) = oq;
        *(float4*)(kT + (size_t)bh*131072 + d*2048 + s0 + s4) = ok;
    }
}

// ---------------------------------------------------------------------------
// Tensor-core flash attention v2.
// fp32 smem (split at fragment load), S/P aliased in-place, softmax
// distributed over all 256 threads (64 rows x 4 chunks, no shuffles).
// Smem ~70.8 KB -> 2 CTAs/SM. Fragment mapping identical to R12 (verified).
// ---------------------------------------------------------------------------
#define LA 68
#define ATT_SMEM ((4*4352 + 704) * 4)

__global__ void __launch_bounds__(256, 2) attn_mma()
{
    extern __shared__ float sm[];
    float* Qs = sm;                 // [d][q]  64 x LA
    float* Ks = sm + 1*4352;        // [d][key]
    float* Vs = sm + 2*4352;        // [key][e]
    float* Ps = sm + 3*4352;        // S^T then P, [key][q] (in-place exp)
    float* mS = sm + 4*4352;        // [64] running max
    float* cS = mS + 64;            // [64] corr / final inv
    float* lS = cS + 64;            // [64] running sum
    float* Mx = lS + 64;            // [4][64] partial max
    float* Sm = Mx + 256;           // [4][64] partial sum

    const int t    = threadIdx.x;
    const int lane = t & 31, wid = t >> 5;
    const int lq   = lane >> 2, lr = lane & 3;
    const int wm   = (wid & 3) << 4;     // q base
    const int wn   = (wid >> 2) << 5;    // key/e base: 0 or 32
    const int qt   = blockIdx.x;         // 0..31
    const int bh   = blockIdx.y;
    const int b    = bh >> 4, h = bh & 15;

    const float* qTp = n_qT + (size_t)bh*131072 + (qt << 6);
    const float* kTp = n_kT + (size_t)bh*131072;
    const float* vp  = n_v + (size_t)(b*2048)*1024 + (h << 6);

    // Stage Q d-major, scaled by 1/8 (exact)
#pragma unroll
    for (int p = 0; p < 4; p++) {
        const int idx = (p << 8) + t;
        const int d = idx >> 4, q4 = (idx & 15) << 2;
        float4 v = *(const float4*)(qTp + d*2048 + q4);
        v.x *= 0.125f; v.y *= 0.125f; v.z *= 0.125f; v.w *= 0.125f;
        *(float4*)&Qs[d*LA + q4] = v;
    }
    if (t < 64) { mS[t] = -1e30f; lS[t] = 0.f; }

    float acc[4][4];
#pragma unroll
    for (int nt = 0; nt < 4; nt++)
#pragma unroll
        for (int f = 0; f < 4; f++) acc[nt][f] = 0.f;

    const int row = t & 63, ck = t >> 6;

    for (int kt = 0; kt < 32; kt++) {
        __syncthreads();   // A: prev PV done reading Vs/Ps; Qs ready on iter 0

        // Stage K [d][key] and V [key][e], plain fp32
#pragma unroll
        for (int p = 0; p < 4; p++) {
            const int idx = (p << 8) + t;
            const int d = idx >> 4, c4 = (idx & 15) << 2;
            *(float4*)&Ks[d*LA + c4] = *(const float4*)(kTp + d*2048 + (kt << 6) + c4);
        }
#pragma unroll
        for (int p = 0; p < 4; p++) {
            const int idx = (p << 8) + t;
            const int r = idx >> 4, e4 = (idx & 15) << 2;
            *(float4*)&Vs[r*LA + e4] = *(const float4*)(vp + (size_t)((kt << 6) + r)*1024 + e4);
        }
        __syncthreads();   // B: tiles staged

        // ---- QK: S[64q x 64key], warp does 16q x 32key, 3-pass split ----
        float sacc[4][4];
#pragma unroll
        for (int nt = 0; nt < 4; nt++)
#pragma unroll
            for (int f = 0; f < 4; f++) sacc[nt][f] = 0.f;

#pragma unroll
        for (int ks = 0; ks < 8; ks++) {
            const int kk = (ks << 3) + lr;
            const int r  = wm + lq;
            unsigned ah[4], al[4];
            float fh, fl;
            cvt_hl(Qs[kk*LA + r],         fh, fl); ah[0]=__float_as_uint(fh); al[0]=__float_as_uint(fl);
            cvt_hl(Qs[kk*LA + r + 8],     fh, fl); ah[1]=__float_as_uint(fh); al[1]=__float_as_uint(fl);
            cvt_hl(Qs[(kk+4)*LA + r],     fh, fl); ah[2]=__float_as_uint(fh); al[2]=__float_as_uint(fl);
            cvt_hl(Qs[(kk+4)*LA + r + 8], fh, fl); ah[3]=__float_as_uint(fh); al[3]=__float_as_uint(fl);
#pragma unroll
            for (int nt = 0; nt < 4; nt++) {
                const int c = wn + (nt << 3) + lq;
                float bh0, bl0, bh1, bl1;
                cvt_hl(Ks[kk*LA + c],     bh0, bl0);
                cvt_hl(Ks[(kk+4)*LA + c], bh1, bl1);
                mma8(sacc[nt], ah, __float_as_uint(bh0), __float_as_uint(bh1));
                mma8(sacc[nt], ah, __float_as_uint(bl0), __float_as_uint(bl1));
                mma8(sacc[nt], al, __float_as_uint(bh0), __float_as_uint(bh1));
            }
        }

        // Store S transposed into Ps[key][q] (bank-permutation store)
#pragma unroll
        for (int nt = 0; nt < 4; nt++) {
            const int cb = wn + (nt << 3) + (lr << 1);
            const int r  = wm + lq;
            Ps[(cb+0)*LA + r]     = sacc[nt][0];
            Ps[(cb+1)*LA + r]     = sacc[nt][1];
            Ps[(cb+0)*LA + r + 8] = sacc[nt][2];
            Ps[(cb+1)*LA + r + 8] = sacc[nt][3];
        }
        __syncthreads();   // C: S complete

        // ---- Softmax distributed: thread = (row, 16-key chunk ck) ----
        float lm = -1e30f;
#pragma unroll
        for (int u = 0; u < 16; u++)
            lm = fmaxf(lm, Ps[((ck << 4) + u)*LA + row]);
        Mx[(ck << 6) + row] = lm;
        __syncthreads();   // D
        if (t < 64) {
            const float mo = mS[t];
            float mn = fmaxf(fmaxf(Mx[t], Mx[64+t]), fmaxf(Mx[128+t], Mx[192+t]));
            mn = fmaxf(mo, mn);
            mS[t] = mn;
            cS[t] = __expf(mo - mn);
        }
        __syncthreads();   // E
        {
            const float mn = mS[row];
            float lsum = 0.f;
#pragma unroll
            for (int u = 0; u < 16; u++) {
                const int j = (ck << 4) + u;
                const float pv = __expf(Ps[j*LA + row] - mn);
                Ps[j*LA + row] = pv;           // in-place: same thread owns slot
                lsum += pv;
            }
            Sm[(ck << 6) + row] = lsum;
        }
        __syncthreads();   // F: P + partial sums ready
        if (t < 64)
            lS[t] = lS[t]*cS[t] + Sm[t] + Sm[64+t] + Sm[128+t] + Sm[192+t];

        // ---- PV: O += P @ V, warp does 16q x 32e, 3-pass split ----
        {
            const float c0 = cS[wm + lq], c1 = cS[wm + lq + 8];
#pragma unroll
            for (int nt = 0; nt < 4; nt++) {
                acc[nt][0] *= c0; acc[nt][1] *= c0;
                acc[nt][2] *= c1; acc[nt][3] *= c1;
            }
#pragma unroll
            for (int ks = 0; ks < 8; ks++) {
                const int kk = (ks << 3) + lr;      // key index
                const int r  = wm + lq;
                unsigned ah[4], al[4];
                float fh, fl;
                cvt_hl(Ps[kk*LA + r],         fh, fl); ah[0]=__float_as_uint(fh); al[0]=__float_as_uint(fl);
                cvt_hl(Ps[kk*LA + r + 8],     fh, fl); ah[1]=__float_as_uint(fh); al[1]=__float_as_uint(fl);
                cvt_hl(Ps[(kk+4)*LA + r],     fh, fl); ah[2]=__float_as_uint(fh); al[2]=__float_as_uint(fl);
                cvt_hl(Ps[(kk+4)*LA + r + 8], fh, fl); ah[3]=__float_as_uint(fh); al[3]=__float_as_uint(fl);
#pragma unroll
                for (int nt = 0; nt < 4; nt++) {
                    const int c = wn + (nt << 3) + lq;   // e col
                    float bh0, bl0, bh1, bl1;
                    cvt_hl(Vs[kk*LA + c],     bh0, bl0);
                    cvt_hl(Vs[(kk+4)*LA + c], bh1, bl1);
                    mma8(acc[nt], ah, __float_as_uint(bh0), __float_as_uint(bh1));
                    mma8(acc[nt], ah, __float_as_uint(bl0), __float_as_uint(bl1));
                    mma8(acc[nt], al, __float_as_uint(bh0), __float_as_uint(bh1));
                }
            }
        }
    }

    __syncthreads();
    if (t < 64) cS[t] = 1.f / lS[t];
    __syncthreads();

    const float i0 = cS[wm + lq], i1 = cS[wm + lq + 8];
#pragma unroll
    for (int nt = 0; nt < 4; nt++) {
        const int q0 = (qt << 6) + wm + lq;
        const int e  = wn + (nt << 3) + (lr << 1);
        const size_t base = (size_t)(b*2048 + q0)*1024 + (h << 6) + e;
        *(float2*)&n_ctx[base]           = make_float2(acc[nt][0]*i0, acc[nt][1]*i0);
        *(float2*)&n_ctx[base + 8*1024]  = make_float2(acc[nt][2]*i1, acc[nt][3]*i1);
    }
}

// ---------------------------------------------------------------------------
extern "C" void kernel_launch(void* const* d_in, const int* in_sizes, int n_in,
                              void* d_out, int out_size)
{
    const float* x  = (const float*)d_in[0];
    const float* Wq = (const float*)d_in[1];
    const float* Wk = (const float*)d_in[2];
    const float* Wv = (const float*)d_in[3];
    const float* Wo = (const float*)d_in[4];
    float* out = (float*)d_out;

    float* gq;  cudaGetSymbolAddress((void**)&gq, n_q);
    float* gk;  cudaGetSymbolAddress((void**)&gk, n_k);
    float* gv;  cudaGetSymbolAddress((void**)&gv, n_v);
    float* gc;  cudaGetSymbolAddress((void**)&gc, n_ctx);
    float* gqT; cudaGetSymbolAddress((void**)&gqT, n_qT);
    float* gkT; cudaGetSymbolAddress((void**)&gkT, n_kT);

    cudaFuncSetAttribute(attn_mma, cudaFuncAttributeMaxDynamicSharedMemorySize, ATT_SMEM);

    gemm_tf32<<<dim3(8, 32, 3), 256>>>(x, Wq, Wk, Wv, gq, gk, gv);
    nrope<<<4096 * 16 * 32 / 256, 256>>>(gq, gk);
    trans_hd<<<dim3(32, 32), 256>>>(gq, gk, gqT, gkT);
    attn_mma<<<dim3(32, 32), 256, ATT_SMEM>>>();
    gemm_tf32<<<dim3(8, 32, 1), 256>>>(gc, Wo, Wo, Wo, out, out, out);
}

// round 15
// speedup vs baseline: 32.6257x; 1.0058x over previous
#include <cuda_runtime.h>
#include <math.h>

// B=2, S=2048, D=1024, H=16, HD=64. Scratch row-major [b*S+s][h*64+e],
// plus per-head transposed+rope'd q/k: [bh][d][s].
__device__ float n_q[4096*1024];
__device__ float n_k[4096*1024];
__device__ float n_v[4096*1024];
__device__ float n_ctx[4096*1024];
__device__ float n_qT[32*64*2048];
__device__ float n_kT[32*64*2048];

// ---------------------------------------------------------------------------
// Split-tf32 helpers (verified R10/R12/R13).
// ---------------------------------------------------------------------------
__device__ __forceinline__ void cvt_hl(float v, float& h, float& l) {
    unsigned u;
    asm("cvt.rna.tf32.f32 %0, %1;" : "=r"(u) : "f"(v));
    h = __uint_as_float(u);
    l = v - h;
}

__device__ __forceinline__ void mma8(float* d, const unsigned* a, unsigned b0, unsigned b1) {
    asm volatile(
        "mma.sync.aligned.m16n8k8.row.col.f32.tf32.tf32.f32 "
        "{%0,%1,%2,%3}, {%4,%5,%6,%7}, {%8,%9}, {%0,%1,%2,%3};"
        : "+f"(d[0]), "+f"(d[1]), "+f"(d[2]), "+f"(d[3])
        : "r"(a[0]), "r"(a[1]), "r"(a[2]), "r"(a[3]), "r"(b0), "r"(b1));
}

// ---------------------------------------------------------------------------
// TF32 GEMM — VERBATIM from passing R13. C = A @ W^T.
// ---------------------------------------------------------------------------
#define LDP 132

__global__ void __launch_bounds__(256) gemm_tf32(
    const float* __restrict__ A,
    const float* __restrict__ W0, const float* __restrict__ W1, const float* __restrict__ W2,
    float* __restrict__ C0, float* __restrict__ C1, float* __restrict__ C2)
{
    const float* W = (blockIdx.z == 0) ? W0 : (blockIdx.z == 1) ? W1 : W2;
    float*       C = (blockIdx.z == 0) ? C0 : (blockIdx.z == 1) ? C1 : C2;

    __shared__ float As[16 * LDP];
    __shared__ float Bs[16 * LDP];

    const int t    = threadIdx.x;
    const int lane = t & 31;
    const int wid  = t >> 5;
    const int wm   = (wid & 3) << 5;
    const int wn   = (wid >> 2) << 6;
    const int m0   = blockIdx.y << 7;
    const int n0   = blockIdx.x << 7;

    const int row0 = t >> 2;
    const int kg   = (t & 3) << 2;

    const int lq = lane >> 2;
    const int lr = lane & 3;

    float acc[2][8][4];
#pragma unroll
    for (int mt = 0; mt < 2; mt++)
#pragma unroll
        for (int nt = 0; nt < 8; nt++)
#pragma unroll
            for (int f = 0; f < 4; f++) acc[mt][nt][f] = 0.f;

    for (int k0 = 0; k0 < 1024; k0 += 16) {
        float4 a0v = *(const float4*)(A + (m0 + row0)      * 1024 + k0 + kg);
        float4 a1v = *(const float4*)(A + (m0 + row0 + 64) * 1024 + k0 + kg);
        float4 b0v = *(const float4*)(W + (n0 + row0)      * 1024 + k0 + kg);
        float4 b1v = *(const float4*)(W + (n0 + row0 + 64) * 1024 + k0 + kg);

        __syncthreads();

        As[(kg+0)*LDP + row0] = a0v.x;
        As[(kg+1)*LDP + row0] = a0v.y;
        As[(kg+2)*LDP + row0] = a0v.z;
        As[(kg+3)*LDP + row0] = a0v.w;
        As[(kg+0)*LDP + row0 + 64] = a1v.x;
        As[(kg+1)*LDP + row0 + 64] = a1v.y;
        As[(kg+2)*LDP + row0 + 64] = a1v.z;
        As[(kg+3)*LDP + row0 + 64] = a1v.w;
        Bs[(kg+0)*LDP + row0] = b0v.x;
        Bs[(kg+1)*LDP + row0] = b0v.y;
        Bs[(kg+2)*LDP + row0] = b0v.z;
        Bs[(kg+3)*LDP + row0] = b0v.w;
        Bs[(kg+0)*LDP + row0 + 64] = b1v.x;
        Bs[(kg+1)*LDP + row0 + 64] = b1v.y;
        Bs[(kg+2)*LDP + row0 + 64] = b1v.z;
        Bs[(kg+3)*LDP + row0 + 64] = b1v.w;

        __syncthreads();

#pragma unroll
        for (int ks = 0; ks < 2; ks++) {
            const int kk = (ks << 3) + lr;

            unsigned ah[2][4], al[2][4];
#pragma unroll
            for (int mt = 0; mt < 2; mt++) {
                const int r = wm + (mt << 4) + lq;
                float h, l;
                cvt_hl(As[kk*LDP + r],         h, l); ah[mt][0]=__float_as_uint(h); al[mt][0]=__float_as_uint(l);
                cvt_hl(As[kk*LDP + r + 8],     h, l); ah[mt][1]=__float_as_uint(h); al[mt][1]=__float_as_uint(l);
                cvt_hl(As[(kk+4)*LDP + r],     h, l); ah[mt][2]=__float_as_uint(h); al[mt][2]=__float_as_uint(l);
                cvt_hl(As[(kk+4)*LDP + r + 8], h, l); ah[mt][3]=__float_as_uint(h); al[mt][3]=__float_as_uint(l);
            }

#pragma unroll
            for (int nt = 0; nt < 8; nt++) {
                const int c = wn + (nt << 3) + lq;
                float bh0, bl0, bh1, bl1;
                cvt_hl(Bs[kk*LDP + c],     bh0, bl0);
                cvt_hl(Bs[(kk+4)*LDP + c], bh1, bl1);
                const unsigned ubh0 = __float_as_uint(bh0), ubh1 = __float_as_uint(bh1);
                const unsigned ubl0 = __float_as_uint(bl0), ubl1 = __float_as_uint(bl1);
#pragma unroll
                for (int mt = 0; mt < 2; mt++) {
                    mma8(acc[mt][nt], ah[mt], ubh0, ubh1);
                    mma8(acc[mt][nt], ah[mt], ubl0, ubl1);
                    mma8(acc[mt][nt], al[mt], ubh0, ubh1);
                }
            }
        }
    }

#pragma unroll
    for (int mt = 0; mt < 2; mt++)
#pragma unroll
        for (int nt = 0; nt < 8; nt++) {
            const int m = m0 + wm + (mt << 4) + lq;
            const int n = n0 + wn + (nt << 3) + (lr << 1);
            *(float2*)&C[m * 1024 + n]       = make_float2(acc[mt][nt][0], acc[mt][nt][1]);
            *(float2*)&C[(m + 8) * 1024 + n] = make_float2(acc[mt][nt][2], acc[mt][nt][3]);
        }
}

// ---------------------------------------------------------------------------
// Fused RoPE + per-head transpose, using ONLY the R8-proven trig idioms
// (powf + separate cosf/sinf; NO sincosf, NO exp2f).
// Reads q,k row-major [b*S+s][h*64+d]; writes rope'd qT,kT [bh][d][s].
// Pair (i, i+32), i = d & 31, angle = s * 10000^(-i/32):
//   d <  32: out = x1*cos - x2*sin
//   d >= 32: out = x2*cos + x1*sin
// ---------------------------------------------------------------------------
__global__ void __launch_bounds__(256) rope_trans(const float* __restrict__ q,
                                                  const float* __restrict__ k,
                                                  float* __restrict__ qT,
                                                  float* __restrict__ kT)
{
    __shared__ float Tq[64 * 65];
    __shared__ float Tk[64 * 65];
    const int t  = threadIdx.x;
    const int s0 = blockIdx.x << 6;
    const int bh = blockIdx.y;
    const int b  = bh >> 4, h = bh & 15;

#pragma unroll
    for (int p = 0; p < 4; p++) {
        const int idx = (p << 8) + t;
        const int sl = idx >> 4, d4 = (idx & 15) << 2;
        const float4 vq = *(const float4*)(q + (size_t)(b*2048 + s0 + sl)*1024 + (h<<6) + d4);
        const float4 vk = *(const float4*)(k + (size_t)(b*2048 + s0 + sl)*1024 + (h<<6) + d4);
        Tq[sl*65 + d4+0] = vq.x; Tq[sl*65 + d4+1] = vq.y;
        Tq[sl*65 + d4+2] = vq.z; Tq[sl*65 + d4+3] = vq.w;
        Tk[sl*65 + d4+0] = vk.x; Tk[sl*65 + d4+1] = vk.y;
        Tk[sl*65 + d4+2] = vk.z; Tk[sl*65 + d4+3] = vk.w;
    }
    __syncthreads();

#pragma unroll
    for (int p = 0; p < 4; p++) {
        const int idx = (p << 8) + t;
        const int d = idx >> 4, s4 = (idx & 15) << 2;
        const int i = d & 31;
        const float freq = powf(10000.0f, -(float)i / 32.0f);
        float4 oq, ok;
        float* poq = (float*)&oq;
        float* pok = (float*)&ok;
#pragma unroll
        for (int u = 0; u < 4; u++) {
            const int sl  = s4 + u;
            const float ang = (float)(s0 + sl) * freq;
            const float c  = cosf(ang);
            const float sn = sinf(ang);
            const float q1 = Tq[sl*65 + i], q2 = Tq[sl*65 + i + 32];
            const float k1 = Tk[sl*65 + i], k2 = Tk[sl*65 + i + 32];
            poq[u] = (d < 32) ? (q1 * c - q2 * sn) : (q2 * c + q1 * sn);
            pok[u] = (d < 32) ? (k1 * c - k2 * sn) : (k2 * c + k1 * sn);
        }
        *(float4*)(qT + (size_t)bh*131072 + d*2048 + s0 + s4) = oq;
        *(float4*)(kT + (size_t)bh*131072 + d*2048 + s0 + s4) = ok;
    }
}

// ---------------------------------------------------------------------------
// Tensor-core flash attention — VERBATIM from passing R13 (occ 2).
// ---------------------------------------------------------------------------
#define LA 68
#define ATT_SMEM ((4*4352 + 704) * 4)

__global__ void __launch_bounds__(256, 2) attn_mma()
{
    extern __shared__ float sm[];
    float* Qs = sm;                 // [d][q]  64 x LA
    float* Ks = sm + 1*4352;        // [d][key]
    float* Vs = sm + 2*4352;        // [key][e]
    float* Ps = sm + 3*4352;        // S^T then P, [key][q] (in-place exp)
    float* mS = sm + 4*4352;        // [64] running max
    float* cS = mS + 64;            // [64] corr / final inv
    float* lS = cS + 64;            // [64] running sum
    float* Mx = lS + 64;            // [4][64] partial max
    float* Sm = Mx + 256;           // [4][64] partial sum

    const int t    = threadIdx.x;
    const int lane = t & 31, wid = t >> 5;
    const int lq   = lane >> 2, lr = lane & 3;
    const int wm   = (wid & 3) << 4;     // q base
    const int wn   = (wid >> 2) << 5;    // key/e base: 0 or 32
    const int qt   = blockIdx.x;         // 0..31
    const int bh   = blockIdx.y;
    const int b    = bh >> 4, h = bh & 15;

    const float* qTp = n_qT + (size_t)bh*131072 + (qt << 6);
    const float* kTp = n_kT + (size_t)bh*131072;
    const float* vp  = n_v + (size_t)(b*2048)*1024 + (h << 6);

    // Stage Q d-major, scaled by 1/8 (exact)
#pragma unroll
    for (int p = 0; p < 4; p++) {
        const int idx = (p << 8) + t;
        const int d = idx >> 4, q4 = (idx & 15) << 2;
        float4 v = *(const float4*)(qTp + d*2048 + q4);
        v.x *= 0.125f; v.y *= 0.125f; v.z *= 0.125f; v.w *= 0.125f;
        *(float4*)&Qs[d*LA + q4] = v;
    }
    if (t < 64) { mS[t] = -1e30f; lS[t] = 0.f; }

    float acc[4][4];
#pragma unroll
    for (int nt = 0; nt < 4; nt++)
#pragma unroll
        for (int f = 0; f < 4; f++) acc[nt][f] = 0.f;

    const int row = t & 63, ck = t >> 6;

    for (int kt = 0; kt < 32; kt++) {
        __syncthreads();   // A: prev PV done reading Vs/Ps; Qs ready on iter 0

        // Stage K [d][key] and V [key][e], plain fp32
#pragma unroll
        for (int p = 0; p < 4; p++) {
            const int idx = (p << 8) + t;
            const int d = idx >> 4, c4 = (idx & 15) << 2;
            *(float4*)&Ks[d*LA + c4] = *(const float4*)(kTp + d*2048 + (kt << 6) + c4);
        }
#pragma unroll
        for (int p = 0; p < 4; p++) {
            const int idx = (p << 8) + t;
            const int r = idx >> 4, e4 = (idx & 15) << 2;
            *(float4*)&Vs[r*LA + e4] = *(const float4*)(vp + (size_t)((kt << 6) + r)*1024 + e4);
        }
        __syncthreads();   // B: tiles staged

        // ---- QK: S[64q x 64key], warp does 16q x 32key, 3-pass split ----
        float sacc[4][4];
#pragma unroll
        for (int nt = 0; nt < 4; nt++)
#pragma unroll
            for (int f = 0; f < 4; f++) sacc[nt][f] = 0.f;

#pragma unroll
        for (int ks = 0; ks < 8; ks++) {
            const int kk = (ks << 3) + lr;
            const int r  = wm + lq;
            unsigned ah[4], al[4];
            float fh, fl;
            cvt_hl(Qs[kk*LA + r],         fh, fl); ah[0]=__float_as_uint(fh); al[0]=__float_as_uint(fl);
            cvt_hl(Qs[kk*LA + r + 8],     fh, fl); ah[1]=__float_as_uint(fh); al[1]=__float_as_uint(fl);
            cvt_hl(Qs[(kk+4)*LA + r],     fh, fl); ah[2]=__float_as_uint(fh); al[2]=__float_as_uint(fl);
            cvt_hl(Qs[(kk+4)*LA + r + 8], fh, fl); ah[3]=__float_as_uint(fh); al[3]=__float_as_uint(fl);
#pragma unroll
            for (int nt = 0; nt < 4; nt++) {
                const int c = wn + (nt << 3) + lq;
                float bh0, bl0, bh1, bl1;
                cvt_hl(Ks[kk*LA + c],     bh0, bl0);
                cvt_hl(Ks[(kk+4)*LA + c], bh1, bl1);
                mma8(sacc[nt], ah, __float_as_uint(bh0), __float_as_uint(bh1));
                mma8(sacc[nt], ah, __float_as_uint(bl0), __float_as_uint(bl1));
                mma8(sacc[nt], al, __float_as_uint(bh0), __float_as_uint(bh1));
            }
        }

        // Store S transposed into Ps[key][q]
#pragma unroll
        for (int nt = 0; nt < 4; nt++) {
            const int cb = wn + (nt << 3) + (lr << 1);
            const int r  = wm + lq;
            Ps[(cb+0)*LA + r]     = sacc[nt][0];
            Ps[(cb+1)*LA + r]     = sacc[nt][1];
            Ps[(cb+0)*LA + r + 8] = sacc[nt][2];
            Ps[(cb+1)*LA + r + 8] = sacc[nt][3];
        }
        __syncthreads();   // C: S complete

        // ---- Softmax distributed: thread = (row, 16-key chunk ck) ----
        float lm = -1e30f;
#pragma unroll
        for (int u = 0; u < 16; u++)
            lm = fmaxf(lm, Ps[((ck << 4) + u)*LA + row]);
        Mx[(ck << 6) + row] = lm;
        __syncthreads();   // D
        if (t < 64) {
            const float mo = mS[t];
            float mn = fmaxf(fmaxf(Mx[t], Mx[64+t]), fmaxf(Mx[128+t], Mx[192+t]));
            mn = fmaxf(mo, mn);
            mS[t] = mn;
            cS[t] = __expf(mo - mn);
        }
        __syncthreads();   // E
        {
            const float mn = mS[row];
            float lsum = 0.f;
#pragma unroll
            for (int u = 0; u < 16; u++) {
                const int j = (ck << 4) + u;
                const float pv = __expf(Ps[j*LA + row] - mn);
                Ps[j*LA + row] = pv;
                lsum += pv;
            }
            Sm[(ck << 6) + row] = lsum;
        }
        __syncthreads();   // F: P + partial sums ready
        if (t < 64)
            lS[t] = lS[t]*cS[t] + Sm[t] + Sm[64+t] + Sm[128+t] + Sm[192+t];

        // ---- PV: O += P @ V, warp does 16q x 32e, 3-pass split ----
        {
            const float c0 = cS[wm + lq], c1 = cS[wm + lq + 8];
#pragma unroll
            for (int nt = 0; nt < 4; nt++) {
                acc[nt][0] *= c0; acc[nt][1] *= c0;
                acc[nt][2] *= c1; acc[nt][3] *= c1;
            }
#pragma unroll
            for (int ks = 0; ks < 8; ks++) {
                const int kk = (ks << 3) + lr;      // key index
                const int r  = wm + lq;
                unsigned ah[4], al[4];
                float fh, fl;
                cvt_hl(Ps[kk*LA + r],         fh, fl); ah[0]=__float_as_uint(fh); al[0]=__float_as_uint(fl);
                cvt_hl(Ps[kk*LA + r + 8],     fh, fl); ah[1]=__float_as_uint(fh); al[1]=__float_as_uint(fl);
                cvt_hl(Ps[(kk+4)*LA + r],     fh, fl); ah[2]=__float_as_uint(fh); al[2]=__float_as_uint(fl);
                cvt_hl(Ps[(kk+4)*LA + r + 8], fh, fl); ah[3]=__float_as_uint(fh); al[3]=__float_as_uint(fl);
#pragma unroll
                for (int nt = 0; nt < 4; nt++) {
                    const int c = wn + (nt << 3) + lq;   // e col
                    float bh0, bl0, bh1, bl1;
                    cvt_hl(Vs[kk*LA + c],     bh0, bl0);
                    cvt_hl(Vs[(kk+4)*LA + c], bh1, bl1);
                    mma8(acc[nt], ah, __float_as_uint(bh0), __float_as_uint(bh1));
                    mma8(acc[nt], ah, __float_as_uint(bl0), __float_as_uint(bl1));
                    mma8(acc[nt], al, __float_as_uint(bh0), __float_as_uint(bh1));
                }
            }
        }
    }

    __syncthreads();
    if (t < 64) cS[t] = 1.f / lS[t];
    __syncthreads();

    const float i0 = cS[wm + lq], i1 = cS[wm + lq + 8];
#pragma unroll
    for (int nt = 0; nt < 4; nt++) {
        const int q0 = (qt << 6) + wm + lq;
        const int e  = wn + (nt << 3) + (lr << 1);
        const size_t base = (size_t)(b*2048 + q0)*1024 + (h << 6) + e;
        *(float2*)&n_ctx[base]           = make_float2(acc[nt][0]*i0, acc[nt][1]*i0);
        *(float2*)&n_ctx[base + 8*1024]  = make_float2(acc[nt][2]*i1, acc[nt][3]*i1);
    }
}

// ---------------------------------------------------------------------------
extern "C" void kernel_launch(void* const* d_in, const int* in_sizes, int n_in,
                              void* d_out, int out_size)
{
    const float* x  = (const float*)d_in[0];
    const float* Wq = (const float*)d_in[1];
    const float* Wk = (const float*)d_in[2];
    const float* Wv = (const float*)d_in[3];
    const float* Wo = (const float*)d_in[4];
    float* out = (float*)d_out;

    float* gq;  cudaGetSymbolAddress((void**)&gq, n_q);
    float* gk;  cudaGetSymbolAddress((void**)&gk, n_k);
    float* gv;  cudaGetSymbolAddress((void**)&gv, n_v);
    float* gc;  cudaGetSymbolAddress((void**)&gc, n_ctx);
    float* gqT; cudaGetSymbolAddress((void**)&gqT, n_qT);
    float* gkT; cudaGetSymbolAddress((void**)&gkT, n_kT);

    cudaFuncSetAttribute(attn_mma, cudaFuncAttributeMaxDynamicSharedMemorySize, ATT_SMEM);

    gemm_tf32<<<dim3(8, 32, 3), 256>>>(x, Wq, Wk, Wv, gq, gk, gv);
    rope_trans<<<dim3(32, 32), 256>>>(gq, gk, gqT, gkT);
    attn_mma<<<dim3(32, 32), 256, ATT_SMEM>>>();
    gemm_tf32<<<dim3(8, 32, 1), 256>>>(gc, Wo, Wo, Wo, out, out, out);
}

// round 16
// speedup vs baseline: 33.2656x; 1.0196x over previous
#include <cuda_runtime.h>
#include <math.h>

// B=2, S=2048, D=1024, H=16, HD=64. Scratch row-major [b*S+s][h*64+e],
// plus per-head transposed+rope'd q/k: [bh][d][s].
__device__ float n_q[4096*1024];
__device__ float n_k[4096*1024];
__device__ float n_v[4096*1024];
__device__ float n_ctx[4096*1024];
__device__ float n_qT[32*64*2048];
__device__ float n_kT[32*64*2048];

// ---------------------------------------------------------------------------
// Split-tf32 helpers (verified R10/R12/R13/R15).
// ---------------------------------------------------------------------------
__device__ __forceinline__ void cvt_hl(float v, float& h, float& l) {
    unsigned u;
    asm("cvt.rna.tf32.f32 %0, %1;" : "=r"(u) : "f"(v));
    h = __uint_as_float(u);
    l = v - h;
}

__device__ __forceinline__ void mma8(float* d, const unsigned* a, unsigned b0, unsigned b1) {
    asm volatile(
        "mma.sync.aligned.m16n8k8.row.col.f32.tf32.tf32.f32 "
        "{%0,%1,%2,%3}, {%4,%5,%6,%7}, {%8,%9}, {%0,%1,%2,%3};"
        : "+f"(d[0]), "+f"(d[1]), "+f"(d[2]), "+f"(d[3])
        : "r"(a[0]), "r"(a[1]), "r"(a[2]), "r"(a[3]), "r"(b0), "r"(b1));
}

// ---------------------------------------------------------------------------
// TF32 GEMM — VERBATIM from passing R13/R15. C = A @ W^T.
// ---------------------------------------------------------------------------
#define LDP 132

__global__ void __launch_bounds__(256) gemm_tf32(
    const float* __restrict__ A,
    const float* __restrict__ W0, const float* __restrict__ W1, const float* __restrict__ W2,
    float* __restrict__ C0, float* __restrict__ C1, float* __restrict__ C2)
{
    const float* W = (blockIdx.z == 0) ? W0 : (blockIdx.z == 1) ? W1 : W2;
    float*       C = (blockIdx.z == 0) ? C0 : (blockIdx.z == 1) ? C1 : C2;

    __shared__ float As[16 * LDP];
    __shared__ float Bs[16 * LDP];

    const int t    = threadIdx.x;
    const int lane = t & 31;
    const int wid  = t >> 5;
    const int wm   = (wid & 3) << 5;
    const int wn   = (wid >> 2) << 6;
    const int m0   = blockIdx.y << 7;
    const int n0   = blockIdx.x << 7;

    const int row0 = t >> 2;
    const int kg   = (t & 3) << 2;

    const int lq = lane >> 2;
    const int lr = lane & 3;

    float acc[2][8][4];
#pragma unroll
    for (int mt = 0; mt < 2; mt++)
#pragma unroll
        for (int nt = 0; nt < 8; nt++)
#pragma unroll
            for (int f = 0; f < 4; f++) acc[mt][nt][f] = 0.f;

    for (int k0 = 0; k0 < 1024; k0 += 16) {
        float4 a0v = *(const float4*)(A + (m0 + row0)      * 1024 + k0 + kg);
        float4 a1v = *(const float4*)(A + (m0 + row0 + 64) * 1024 + k0 + kg);
        float4 b0v = *(const float4*)(W + (n0 + row0)      * 1024 + k0 + kg);
        float4 b1v = *(const float4*)(W + (n0 + row0 + 64) * 1024 + k0 + kg);

        __syncthreads();

        As[(kg+0)*LDP + row0] = a0v.x;
        As[(kg+1)*LDP + row0] = a0v.y;
        As[(kg+2)*LDP + row0] = a0v.z;
        As[(kg+3)*LDP + row0] = a0v.w;
        As[(kg+0)*LDP + row0 + 64] = a1v.x;
        As[(kg+1)*LDP + row0 + 64] = a1v.y;
        As[(kg+2)*LDP + row0 + 64] = a1v.z;
        As[(kg+3)*LDP + row0 + 64] = a1v.w;
        Bs[(kg+0)*LDP + row0] = b0v.x;
        Bs[(kg+1)*LDP + row0] = b0v.y;
        Bs[(kg+2)*LDP + row0] = b0v.z;
        Bs[(kg+3)*LDP + row0] = b0v.w;
        Bs[(kg+0)*LDP + row0 + 64] = b1v.x;
        Bs[(kg+1)*LDP + row0 + 64] = b1v.y;
        Bs[(kg+2)*LDP + row0 + 64] = b1v.z;
        Bs[(kg+3)*LDP + row0 + 64] = b1v.w;

        __syncthreads();

#pragma unroll
        for (int ks = 0; ks < 2; ks++) {
            const int kk = (ks << 3) + lr;

            unsigned ah[2][4], al[2][4];
#pragma unroll
            for (int mt = 0; mt < 2; mt++) {
                const int r = wm + (mt << 4) + lq;
                float h, l;
                cvt_hl(As[kk*LDP + r],         h, l); ah[mt][0]=__float_as_uint(h); al[mt][0]=__float_as_uint(l);
                cvt_hl(As[kk*LDP + r + 8],     h, l); ah[mt][1]=__float_as_uint(h); al[mt][1]=__float_as_uint(l);
                cvt_hl(As[(kk+4)*LDP + r],     h, l); ah[mt][2]=__float_as_uint(h); al[mt][2]=__float_as_uint(l);
                cvt_hl(As[(kk+4)*LDP + r + 8], h, l); ah[mt][3]=__float_as_uint(h); al[mt][3]=__float_as_uint(l);
            }

#pragma unroll
            for (int nt = 0; nt < 8; nt++) {
                const int c = wn + (nt << 3) + lq;
                float bh0, bl0, bh1, bl1;
                cvt_hl(Bs[kk*LDP + c],     bh0, bl0);
                cvt_hl(Bs[(kk+4)*LDP + c], bh1, bl1);
                const unsigned ubh0 = __float_as_uint(bh0), ubh1 = __float_as_uint(bh1);
                const unsigned ubl0 = __float_as_uint(bl0), ubl1 = __float_as_uint(bl1);
#pragma unroll
                for (int mt = 0; mt < 2; mt++) {
                    mma8(acc[mt][nt], ah[mt], ubh0, ubh1);
                    mma8(acc[mt][nt], ah[mt], ubl0, ubl1);
                    mma8(acc[mt][nt], al[mt], ubh0, ubh1);
                }
            }
        }
    }

#pragma unroll
    for (int mt = 0; mt < 2; mt++)
#pragma unroll
        for (int nt = 0; nt < 8; nt++) {
            const int m = m0 + wm + (mt << 4) + lq;
            const int n = n0 + wn + (nt << 3) + (lr << 1);
            *(float2*)&C[m * 1024 + n]       = make_float2(acc[mt][nt][0], acc[mt][nt][1]);
            *(float2*)&C[(m + 8) * 1024 + n] = make_float2(acc[mt][nt][2], acc[mt][nt][3]);
        }
}

// ---------------------------------------------------------------------------
// Fused RoPE + per-head transpose — VERBATIM from passing R15
// (powf + separate cosf/sinf; NO sincosf, NO exp2f).
// ---------------------------------------------------------------------------
__global__ void __launch_bounds__(256) rope_trans(const float* __restrict__ q,
                                                  const float* __restrict__ k,
                                                  float* __restrict__ qT,
                                                  float* __restrict__ kT)
{
    __shared__ float Tq[64 * 65];
    __shared__ float Tk[64 * 65];
    const int t  = threadIdx.x;
    const int s0 = blockIdx.x << 6;
    const int bh = blockIdx.y;
    const int b  = bh >> 4, h = bh & 15;

#pragma unroll
    for (int p = 0; p < 4; p++) {
        const int idx = (p << 8) + t;
        const int sl = idx >> 4, d4 = (idx & 15) << 2;
        const float4 vq = *(const float4*)(q + (size_t)(b*2048 + s0 + sl)*1024 + (h<<6) + d4);
        const float4 vk = *(const float4*)(k + (size_t)(b*2048 + s0 + sl)*1024 + (h<<6) + d4);
        Tq[sl*65 + d4+0] = vq.x; Tq[sl*65 + d4+1] = vq.y;
        Tq[sl*65 + d4+2] = vq.z; Tq[sl*65 + d4+3] = vq.w;
        Tk[sl*65 + d4+0] = vk.x; Tk[sl*65 + d4+1] = vk.y;
        Tk[sl*65 + d4+2] = vk.z; Tk[sl*65 + d4+3] = vk.w;
    }
    __syncthreads();

#pragma unroll
    for (int p = 0; p < 4; p++) {
        const int idx = (p << 8) + t;
        const int d = idx >> 4, s4 = (idx & 15) << 2;
        const int i = d & 31;
        const float freq = powf(10000.0f, -(float)i / 32.0f);
        float4 oq, ok;
        float* poq = (float*)&oq;
        float* pok = (float*)&ok;
#pragma unroll
        for (int u = 0; u < 4; u++) {
            const int sl  = s4 + u;
            const float ang = (float)(s0 + sl) * freq;
            const float c  = cosf(ang);
            const float sn = sinf(ang);
            const float q1 = Tq[sl*65 + i], q2 = Tq[sl*65 + i + 32];
            const float k1 = Tk[sl*65 + i], k2 = Tk[sl*65 + i + 32];
            poq[u] = (d < 32) ? (q1 * c - q2 * sn) : (q2 * c + q1 * sn);
            pok[u] = (d < 32) ? (k1 * c - k2 * sn) : (k2 * c + k1 * sn);
        }
        *(float4*)(qT + (size_t)bh*131072 + d*2048 + s0 + s4) = oq;
        *(float4*)(kT + (size_t)bh*131072 + d*2048 + s0 + s4) = ok;
    }
}

// ---------------------------------------------------------------------------
// Tensor-core flash attention — R15 body, SINGLE CHANGE: occupancy 2 -> 3.
// Smem 72.4 KB x 3 = 217 KB <= 228 KB; regs capped 96 -> 85.
// ---------------------------------------------------------------------------
#define LA 68
#define ATT_SMEM ((4*4352 + 704) * 4)

__global__ void __launch_bounds__(256, 3) attn_mma()
{
    extern __shared__ float sm[];
    float* Qs = sm;                 // [d][q]  64 x LA
    float* Ks = sm + 1*4352;        // [d][key]
    float* Vs = sm + 2*4352;        // [key][e]
    float* Ps = sm + 3*4352;        // S^T then P, [key][q] (in-place exp)
    float* mS = sm + 4*4352;        // [64] running max
    float* cS = mS + 64;            // [64] corr / final inv
    float* lS = cS + 64;            // [64] running sum
    float* Mx = lS + 64;            // [4][64] partial max
    float* Sm = Mx + 256;           // [4][64] partial sum

    const int t    = threadIdx.x;
    const int lane = t & 31, wid = t >> 5;
    const int lq   = lane >> 2, lr = lane & 3;
    const int wm   = (wid & 3) << 4;     // q base
    const int wn   = (wid >> 2) << 5;    // key/e base: 0 or 32
    const int qt   = blockIdx.x;         // 0..31
    const int bh   = blockIdx.y;
    const int b    = bh >> 4, h = bh & 15;

    const float* qTp = n_qT + (size_t)bh*131072 + (qt << 6);
    const float* kTp = n_kT + (size_t)bh*131072;
    const float* vp  = n_v + (size_t)(b*2048)*1024 + (h << 6);

    // Stage Q d-major, scaled by 1/8 (exact)
#pragma unroll
    for (int p = 0; p < 4; p++) {
        const int idx = (p << 8) + t;
        const int d = idx >> 4, q4 = (idx & 15) << 2;
        float4 v = *(const float4*)(qTp + d*2048 + q4);
        v.x *= 0.125f; v.y *= 0.125f; v.z *= 0.125f; v.w *= 0.125f;
        *(float4*)&Qs[d*LA + q4] = v;
    }
    if (t < 64) { mS[t] = -1e30f; lS[t] = 0.f; }

    float acc[4][4];
#pragma unroll
    for (int nt = 0; nt < 4; nt++)
#pragma unroll
        for (int f = 0; f < 4; f++) acc[nt][f] = 0.f;

    const int row = t & 63, ck = t >> 6;

    for (int kt = 0; kt < 32; kt++) {
        __syncthreads();   // A: prev PV done reading Vs/Ps; Qs ready on iter 0

        // Stage K [d][key] and V [key][e], plain fp32
#pragma unroll
        for (int p = 0; p < 4; p++) {
            const int idx = (p << 8) + t;
            const int d = idx >> 4, c4 = (idx & 15) << 2;
            *(float4*)&Ks[d*LA + c4] = *(const float4*)(kTp + d*2048 + (kt << 6) + c4);
        }
#pragma unroll
        for (int p = 0; p < 4; p++) {
            const int idx = (p << 8) + t;
            const int r = idx >> 4, e4 = (idx & 15) << 2;
            *(float4*)&Vs[r*LA + e4] = *(const float4*)(vp + (size_t)((kt << 6) + r)*1024 + e4);
        }
        __syncthreads();   // B: tiles staged

        // ---- QK: S[64q x 64key], warp does 16q x 32key, 3-pass split ----
        float sacc[4][4];
#pragma unroll
        for (int nt = 0; nt < 4; nt++)
#pragma unroll
            for (int f = 0; f < 4; f++) sacc[nt][f] = 0.f;

#pragma unroll
        for (int ks = 0; ks < 8; ks++) {
            const int kk = (ks << 3) + lr;
            const int r  = wm + lq;
            unsigned ah[4], al[4];
            float fh, fl;
            cvt_hl(Qs[kk*LA + r],         fh, fl); ah[0]=__float_as_uint(fh); al[0]=__float_as_uint(fl);
            cvt_hl(Qs[kk*LA + r + 8],     fh, fl); ah[1]=__float_as_uint(fh); al[1]=__float_as_uint(fl);
            cvt_hl(Qs[(kk+4)*LA + r],     fh, fl); ah[2]=__float_as_uint(fh); al[2]=__float_as_uint(fl);
            cvt_hl(Qs[(kk+4)*LA + r + 8], fh, fl); ah[3]=__float_as_uint(fh); al[3]=__float_as_uint(fl);
#pragma unroll
            for (int nt = 0; nt < 4; nt++) {
                const int c = wn + (nt << 3) + lq;
                float bh0, bl0, bh1, bl1;
                cvt_hl(Ks[kk*LA + c],     bh0, bl0);
                cvt_hl(Ks[(kk+4)*LA + c], bh1, bl1);
                mma8(sacc[nt], ah, __float_as_uint(bh0), __float_as_uint(bh1));
                mma8(sacc[nt], ah, __float_as_uint(bl0), __float_as_uint(bl1));
                mma8(sacc[nt], al, __float_as_uint(bh0), __float_as_uint(bh1));
            }
        }

        // Store S transposed into Ps[key][q]
#pragma unroll
        for (int nt = 0; nt < 4; nt++) {
            const int cb = wn + (nt << 3) + (lr << 1);
            const int r  = wm + lq;
            Ps[(cb+0)*LA + r]     = sacc[nt][0];
            Ps[(cb+1)*LA + r]     = sacc[nt][1];
            Ps[(cb+0)*LA + r + 8] = sacc[nt][2];
            Ps[(cb+1)*LA + r + 8] = sacc[nt][3];
        }
        __syncthreads();   // C: S complete

        // ---- Softmax distributed: thread = (row, 16-key chunk ck) ----
        float lm = -1e30f;
#pragma unroll
        for (int u = 0; u < 16; u++)
            lm = fmaxf(lm, Ps[((ck << 4) + u)*LA + row]);
        Mx[(ck << 6) + row] = lm;
        __syncthreads();   // D
        if (t < 64) {
            const float mo = mS[t];
            float mn = fmaxf(fmaxf(Mx[t], Mx[64+t]), fmaxf(Mx[128+t], Mx[192+t]));
            mn = fmaxf(mo, mn);
            mS[t] = mn;
            cS[t] = __expf(mo - mn);
        }
        __syncthreads();   // E
        {
            const float mn = mS[row];
            float lsum = 0.f;
#pragma unroll
            for (int u = 0; u < 16; u++) {
                const int j = (ck << 4) + u;
                const float pv = __expf(Ps[j*LA + row] - mn);
                Ps[j*LA + row] = pv;
                lsum += pv;
            }
            Sm[(ck << 6) + row] = lsum;
        }
        __syncthreads();   // F: P + partial sums ready
        if (t < 64)
            lS[t] = lS[t]*cS[t] + Sm[t] + Sm[64+t] + Sm[128+t] + Sm[192+t];

        // ---- PV: O += P @ V, warp does 16q x 32e, 3-pass split ----
        {
            const float c0 = cS[wm + lq], c1 = cS[wm + lq + 8];
#pragma unroll
            for (int nt = 0; nt < 4; nt++) {
                acc[nt][0] *= c0; acc[nt][1] *= c0;
                acc[nt][2] *= c1; acc[nt][3] *= c1;
            }
#pragma unroll
            for (int ks = 0; ks < 8; ks++) {
                const int kk = (ks << 3) + lr;      // key index
                const int r  = wm + lq;
                unsigned ah[4], al[4];
                float fh, fl;
                cvt_hl(Ps[kk*LA + r],         fh, fl); ah[0]=__float_as_uint(fh); al[0]=__float_as_uint(fl);
                cvt_hl(Ps[kk*LA + r + 8],     fh, fl); ah[1]=__float_as_uint(fh); al[1]=__float_as_uint(fl);
                cvt_hl(Ps[(kk+4)*LA + r],     fh, fl); ah[2]=__float_as_uint(fh); al[2]=__float_as_uint(fl);
                cvt_hl(Ps[(kk+4)*LA + r + 8], fh, fl); ah[3]=__float_as_uint(fh); al[3]=__float_as_uint(fl);
#pragma unroll
                for (int nt = 0; nt < 4; nt++) {
                    const int c = wn + (nt << 3) + lq;   // e col
                    float bh0, bl0, bh1, bl1;
                    cvt_hl(Vs[kk*LA + c],     bh0, bl0);
                    cvt_hl(Vs[(kk+4)*LA + c], bh1, bl1);
                    mma8(acc[nt], ah, __float_as_uint(bh0), __float_as_uint(bh1));
                    mma8(acc[nt], ah, __float_as_uint(bl0), __float_as_uint(bl1));
                    mma8(acc[nt], al, __float_as_uint(bh0), __float_as_uint(bh1));
                }
            }
        }
    }

    __syncthreads();
    if (t < 64) cS[t] = 1.f / lS[t];
    __syncthreads();

    const float i0 = cS[wm + lq], i1 = cS[wm + lq + 8];
#pragma unroll
    for (int nt = 0; nt < 4; nt++) {
        const int q0 = (qt << 6) + wm + lq;
        const int e  = wn + (nt << 3) + (lr << 1);
        const size_t base = (size_t)(b*2048 + q0)*1024 + (h << 6) + e;
        *(float2*)&n_ctx[base]           = make_float2(acc[nt][0]*i0, acc[nt][1]*i0);
        *(float2*)&n_ctx[base + 8*1024]  = make_float2(acc[nt][2]*i1, acc[nt][3]*i1);
    }
}

// ---------------------------------------------------------------------------
extern "C" void kernel_launch(void* const* d_in, const int* in_sizes, int n_in,
                              void* d_out, int out_size)
{
    const float* x  = (const float*)d_in[0];
    const float* Wq = (const float*)d_in[1];
    const float* Wk = (const float*)d_in[2];
    const float* Wv = (const float*)d_in[3];
    const float* Wo = (const float*)d_in[4];
    float* out = (float*)d_out;

    float* gq;  cudaGetSymbolAddress((void**)&gq, n_q);
    float* gk;  cudaGetSymbolAddress((void**)&gk, n_k);
    float* gv;  cudaGetSymbolAddress((void**)&gv, n_v);
    float* gc;  cudaGetSymbolAddress((void**)&gc, n_ctx);
    float* gqT; cudaGetSymbolAddress((void**)&gqT, n_qT);
    float* gkT; cudaGetSymbolAddress((void**)&gkT, n_kT);

    cudaFuncSetAttribute(attn_mma, cudaFuncAttributeMaxDynamicSharedMemorySize, ATT_SMEM);

    gemm_tf32<<<dim3(8, 32, 3), 256>>>(x, Wq, Wk, Wv, gq, gk, gv);
    rope_trans<<<dim3(32, 32), 256>>>(gq, gk, gqT, gkT);
    attn_mma<<<dim3(32, 32), 256, ATT_SMEM>>>();
    gemm_tf32<<<dim3(8, 32, 1), 256>>>(gc, Wo, Wo, Wo, out, out, out);
}